// round 8
// baseline (speedup 1.0000x reference)
#include <cuda_runtime.h>
#include <cuda_fp16.h>
#include <cstdint>

// ---------------------------------------------------------------------------
// DynamicProjectionModule via pure-fp16 mma.sync (arch-portable; tcgen05 is
// rejected by the harness's plain compute_103 PTX pass).
//
// Accuracy: A and B rounded to fp16, fp32 accumulation -> rel_err 2.9e-4
// (measured), 3.4x under the 1e-3 gate. Router uses fp64 accumulation so the
// STE argmax matches jax's fp32 scores.
//
// Round 8: overhead strip. (1) tile scheduling computed per-CTA from
// blockIdx + g_cnt (serial build_sched kernel removed); (2) activation
// fp32->fp16 convert fused into the router's existing streaming pass.
// GEMM core unchanged: it saturates the legacy HMMA pipe (~18-25 cyc/SMSP
// effective per m16n8k16).
// ---------------------------------------------------------------------------

#define BSZ      8
#define SEQ      1024
#define IMG_DIM  1024
#define TXT_DIM  768
#define INNER    1024
#define MROWS    (BSZ * SEQ)
#define TELEMS   ((long long)MROWS * INNER)

// ---- device scratch --------------------------------------------------------
__device__ int g_cnt[6];
__device__ int g_list[6][MROWS];

__device__ __half c_img[MROWS * IMG_DIM];
__device__ __half c_txt[MROWS * TXT_DIM];
__device__ __half c_wq [INNER * IMG_DIM];
__device__ __half c_wk [INNER * TXT_DIM];
__device__ __half c_wv [INNER * TXT_DIM];
__device__ __half c_wqb[3 * INNER * IMG_DIM];
__device__ __half c_wkb[3 * INNER * TXT_DIM];

// ---- helpers ---------------------------------------------------------------
__device__ __forceinline__ uint32_t smem_u32(const void* p) {
    uint32_t a;
    asm("{ .reg .u64 t; cvta.to.shared.u64 t, %1; cvt.u32.u64 %0, t; }" : "=r"(a) : "l"(p));
    return a;
}
__device__ __forceinline__ void cp16(uint32_t d, const void* g) {
    asm volatile("cp.async.cg.shared.global [%0], [%1], 16;" :: "r"(d), "l"(g));
}
__device__ __forceinline__ void cp_commit() { asm volatile("cp.async.commit_group;" ::: "memory"); }
template<int N> __device__ __forceinline__ void cp_wait() {
    asm volatile("cp.async.wait_group %0;" :: "n"(N) : "memory");
}
__device__ __forceinline__ void ldsm_x4(uint32_t& r0, uint32_t& r1, uint32_t& r2, uint32_t& r3,
                                        uint32_t addr) {
    asm volatile("ldmatrix.sync.aligned.m8n8.x4.shared.b16 {%0,%1,%2,%3}, [%4];"
                 : "=r"(r0), "=r"(r1), "=r"(r2), "=r"(r3) : "r"(addr));
}
__device__ __forceinline__ void mma16816(float* c, const uint32_t* a, const uint32_t* b) {
    asm volatile("mma.sync.aligned.m16n8k16.row.col.f32.f16.f16.f32 "
                 "{%0,%1,%2,%3}, {%4,%5,%6,%7}, {%8,%9}, {%0,%1,%2,%3};"
                 : "+f"(c[0]), "+f"(c[1]), "+f"(c[2]), "+f"(c[3])
                 : "r"(a[0]), "r"(a[1]), "r"(a[2]), "r"(a[3]), "r"(b[0]), "r"(b[1]));
}
#define SWZ(x) ((x) ^ (((x) >> 3) & 0x70))

// ---- setup -----------------------------------------------------------------
__global__ void init_kernel() {
    if (threadIdx.x < 6) g_cnt[threadIdx.x] = 0;
}

// Fused: fp64-accumulated routing + fp32->fp16 activation convert.
// One warp per token row; streams the row once (float4/lane), emits fp16 copy,
// accumulates the 3 routing scores in fp64, argmax -> compacted bank list.
__global__ void route_conv_kernel(const float* __restrict__ img,
                                  const float* __restrict__ txt,
                                  const float* __restrict__ Wrq,
                                  const float* __restrict__ Wrk) {
    int warp = (blockIdx.x * blockDim.x + threadIdx.x) >> 5;
    int lane = threadIdx.x & 31;
    int side = blockIdx.y;
    if (warp >= MROWS) return;

    const float* x;  const float* wr;  __half* y;  int dim;
    if (side == 0) { x = img + (size_t)warp * IMG_DIM; wr = Wrq;
                     y = c_img + (size_t)warp * IMG_DIM; dim = IMG_DIM; }
    else           { x = txt + (size_t)warp * TXT_DIM; wr = Wrk;
                     y = c_txt + (size_t)warp * TXT_DIM; dim = TXT_DIM; }

    double s0 = 0, s1 = 0, s2 = 0;
    for (int k0 = 0; k0 < dim; k0 += 128) {
        int k = k0 + lane * 4;
        float4 xv = *reinterpret_cast<const float4*>(x + k);

        __half2 h0 = __floats2half2_rn(xv.x, xv.y);
        __half2 h1 = __floats2half2_rn(xv.z, xv.w);
        uint2 o;
        o.x = *reinterpret_cast<uint32_t*>(&h0);
        o.y = *reinterpret_cast<uint32_t*>(&h1);
        *reinterpret_cast<uint2*>(y + k) = o;

        float4 w0 = *reinterpret_cast<const float4*>(wr + k);
        float4 w1 = *reinterpret_cast<const float4*>(wr + dim + k);
        float4 w2 = *reinterpret_cast<const float4*>(wr + 2 * dim + k);
        s0 += (double)xv.x * w0.x + (double)xv.y * w0.y
            + (double)xv.z * w0.z + (double)xv.w * w0.w;
        s1 += (double)xv.x * w1.x + (double)xv.y * w1.y
            + (double)xv.z * w1.z + (double)xv.w * w1.w;
        s2 += (double)xv.x * w2.x + (double)xv.y * w2.y
            + (double)xv.z * w2.z + (double)xv.w * w2.w;
    }
    #pragma unroll
    for (int off = 16; off; off >>= 1) {
        s0 += __shfl_down_sync(0xffffffffu, s0, off);
        s1 += __shfl_down_sync(0xffffffffu, s1, off);
        s2 += __shfl_down_sync(0xffffffffu, s2, off);
    }
    if (lane == 0) {
        int p = 0; double best = s0;
        if (s1 > best) { best = s1; p = 1; }
        if (s2 > best) { best = s2; p = 2; }
        int pos = atomicAdd(&g_cnt[side * 3 + p], 1);
        g_list[side * 3 + p][pos] = warp;
    }
}

// Fused fp32 -> fp16 cast over the 5 weight tensors, 8 elem/unit.
struct WConvArgs {
    const float* src[5];
    __half*      dst[5];
    int          end[5];
};
__global__ void wconvert_kernel(WConvArgs a) {
    const int total = a.end[4];
    const int stride = gridDim.x * blockDim.x;
    for (int i = blockIdx.x * blockDim.x + threadIdx.x; i < total; i += stride) {
        int s = 0;
        #pragma unroll
        for (int t = 0; t < 4; t++) s += (i >= a.end[t]);
        int j = i - (s ? a.end[s - 1] : 0);
        const float4* p = reinterpret_cast<const float4*>(a.src[s]) + 2 * (size_t)j;
        float4 x = p[0], y = p[1];
        __half2 h0 = __floats2half2_rn(x.x, x.y);
        __half2 h1 = __floats2half2_rn(x.z, x.w);
        __half2 h2 = __floats2half2_rn(y.x, y.y);
        __half2 h3 = __floats2half2_rn(y.z, y.w);
        uint4 o;
        o.x = *reinterpret_cast<uint32_t*>(&h0);
        o.y = *reinterpret_cast<uint32_t*>(&h1);
        o.z = *reinterpret_cast<uint32_t*>(&h2);
        o.w = *reinterpret_cast<uint32_t*>(&h3);
        reinterpret_cast<uint4*>(a.dst[s])[j] = o;
    }
}

// ---- fused HMMA GEMM -------------------------------------------------------
// CTA tile 128(M) x 256(N), K-chunk 64, 3-stage cp.async, SW128 swizzle.
// 8 warps as 2(M) x 4(N); warp tile 64x64.  grid = (324, 4):
//   bx <  192          -> Q/K/V static tiles (64 each)
//   192 <= bx < 258    -> routed img banks (prefix over g_cnt[0..2])
//   258 <= bx < 324    -> routed txt banks (prefix over g_cnt[3..5])
#define KC        64
#define A_BYTES   (128 * 128)
#define B_BYTES   (256 * 128)
#define STG_BYTES (A_BYTES + B_BYTES)
#define STAGES    3
#define CTRL_OFF  (STAGES * STG_BYTES)    /* 144 KB */
#define SMEM_TOTAL (CTRL_OFF + 512)
#define GRID_X    324

__global__ void __launch_bounds__(256, 1)
hmma_gemm(float* __restrict__ out)
{
    extern __shared__ char smem[];
    const int bx = blockIdx.x;

    const __half* A;  const __half* W;
    long long outBase;  int K, slot, rowBase;

    if (bx < 192) {
        int g = bx >> 6, t = bx & 63;
        rowBase = t * 128;  slot = -1;
        if (g == 0)      { A = c_img; W = c_wq; outBase = 0;          K = IMG_DIM; }
        else if (g == 1) { A = c_txt; W = c_wk; outBase = TELEMS;     K = TXT_DIM; }
        else             { A = c_txt; W = c_wv; outBase = 2 * TELEMS; K = TXT_DIM; }
    } else if (bx < 258) {
        int t = bx - 192;
        int c0 = (g_cnt[0] + 127) >> 7, c1 = (g_cnt[1] + 127) >> 7,
            c2 = (g_cnt[2] + 127) >> 7;
        int p, loc;
        if (t < c0)            { p = 0; loc = t; }
        else if (t < c0 + c1)  { p = 1; loc = t - c0; }
        else if (t < c0 + c1 + c2) { p = 2; loc = t - c0 - c1; }
        else return;
        A = c_img;  W = c_wqb + (size_t)p * INNER * IMG_DIM;
        outBase = 3 * TELEMS;  K = IMG_DIM;  slot = p;  rowBase = loc * 128;
    } else {
        int t = bx - 258;
        int c0 = (g_cnt[3] + 127) >> 7, c1 = (g_cnt[4] + 127) >> 7,
            c2 = (g_cnt[5] + 127) >> 7;
        int p, loc;
        if (t < c0)            { p = 0; loc = t; }
        else if (t < c0 + c1)  { p = 1; loc = t - c0; }
        else if (t < c0 + c1 + c2) { p = 2; loc = t - c0 - c1; }
        else return;
        A = c_txt;  W = c_wkb + (size_t)p * INNER * TXT_DIM;
        outBase = 4 * TELEMS;  K = TXT_DIM;  slot = 3 + p;  rowBase = loc * 128;
    }

    const int NCHUNK = K / KC;
    const int colBase = blockIdx.y * 256;
    const int cnt = (slot >= 0) ? g_cnt[slot] : MROWS;

    const int tid  = threadIdx.x;
    const int wid  = tid >> 5;
    const int lane = tid & 31;

    const uint32_t sb = smem_u32(smem);
    int* s_rowmap = (int*)(smem + CTRL_OFF);
    if (tid < 128) {
        int gr = rowBase + tid;
        s_rowmap[tid] = (slot < 0) ? gr : ((gr < cnt) ? g_list[slot][gr] : 0);
    }
    __syncthreads();

    const int wm = (wid & 1) * 64;
    const int wn = (wid >> 1) * 64;

    auto load_stage = [&](int buf, int chunk) {
        const int kc = chunk * KC;
        const uint32_t base = sb + buf * STG_BYTES;
        #pragma unroll
        for (int j = 0; j < 4; j++) {
            int t = tid + j * 256;
            int r = t >> 3, c = t & 7;
            const __half* g = A + (size_t)s_rowmap[r] * K + kc + c * 8;
            cp16(base + SWZ(r * 128 + c * 16), g);
        }
        #pragma unroll
        for (int j = 0; j < 8; j++) {
            int t = tid + j * 256;
            int r = t >> 3, c = t & 7;
            const __half* g = W + (size_t)(colBase + r) * K + kc + c * 8;
            cp16(base + A_BYTES + SWZ(r * 128 + c * 16), g);
        }
    };

    float acc[4][8][4];
    #pragma unroll
    for (int m = 0; m < 4; m++)
        #pragma unroll
        for (int n = 0; n < 8; n++)
            #pragma unroll
            for (int q = 0; q < 4; q++) acc[m][n][q] = 0.f;

    load_stage(0, 0); cp_commit();
    load_stage(1, 1); cp_commit();

    for (int c = 0; c < NCHUNK; c++) {
        const int buf = c % STAGES;
        cp_wait<STAGES - 2>();
        __syncthreads();

        if (c + 2 < NCHUNK) load_stage((c + 2) % STAGES, c + 2);
        cp_commit();

        const uint32_t aB = sb + buf * STG_BYTES;
        const uint32_t bB = aB + A_BYTES;

        #pragma unroll
        for (int ks = 0; ks < 4; ks++) {
            uint32_t a[4][4];
            #pragma unroll
            for (int m = 0; m < 4; m++) {
                int row = wm + m * 16 + (lane & 15);
                int c16 = ks * 2 + (lane >> 4);
                ldsm_x4(a[m][0], a[m][1], a[m][2], a[m][3],
                        aB + SWZ(row * 128 + c16 * 16));
            }
            uint32_t b[8][2];
            #pragma unroll
            for (int t = 0; t < 4; t++) {
                int nrow = wn + t * 16 + (lane & 7) + ((lane >> 4) << 3);
                int c16  = ks * 2 + ((lane >> 3) & 1);
                uint32_t r0, r1, r2, r3;
                ldsm_x4(r0, r1, r2, r3, bB + SWZ(nrow * 128 + c16 * 16));
                b[2 * t][0] = r0;     b[2 * t][1] = r1;
                b[2 * t + 1][0] = r2; b[2 * t + 1][1] = r3;
            }
            #pragma unroll
            for (int m = 0; m < 4; m++)
                #pragma unroll
                for (int n = 0; n < 8; n++)
                    mma16816(acc[m][n], a[m], b[n]);
        }
        __syncthreads();
    }

    const int head = (colBase + wn) >> 6;
    #pragma unroll
    for (int m = 0; m < 4; m++) {
        #pragma unroll
        for (int half = 0; half < 2; half++) {
            int rr = wm + m * 16 + (lane >> 2) + half * 8;
            if (rowBase + rr >= cnt) continue;
            int mt = s_rowmap[rr];
            int bb = mt >> 10, sq = mt & 1023;
            long long off0 = outBase + (((long long)(bb * 16 + head) * 1024 + sq) * 64);
            #pragma unroll
            for (int n = 0; n < 8; n++) {
                int dd = n * 8 + 2 * (lane & 3);
                float2 v = make_float2(acc[m][n][half * 2], acc[m][n][half * 2 + 1]);
                *reinterpret_cast<float2*>(out + off0 + dd) = v;
            }
        }
    }
}

// ---- host ------------------------------------------------------------------
extern "C" void kernel_launch(void* const* d_in, const int* in_sizes, int n_in,
                              void* d_out, int out_size) {
    (void)in_sizes; (void)n_in; (void)out_size;
    const float* img = (const float*)d_in[0];
    const float* txt = (const float*)d_in[1];
    const float* Wq  = (const float*)d_in[2];
    const float* Wk  = (const float*)d_in[3];
    const float* Wv  = (const float*)d_in[4];
    const float* Wqb = (const float*)d_in[5];
    const float* Wkb = (const float*)d_in[6];
    const float* Wrq = (const float*)d_in[7];
    const float* Wrk = (const float*)d_in[8];
    float* out = (float*)d_out;

    cudaFuncSetAttribute(hmma_gemm, cudaFuncAttributeMaxDynamicSharedMemorySize,
                         SMEM_TOTAL);

    init_kernel<<<1, 32>>>();
    route_conv_kernel<<<dim3(1024, 2), 256>>>(img, txt, Wrq, Wrk);

    __half *p_wq, *p_wk, *p_wv, *p_wqb, *p_wkb;
    cudaGetSymbolAddress((void**)&p_wq,  c_wq);
    cudaGetSymbolAddress((void**)&p_wk,  c_wk);
    cudaGetSymbolAddress((void**)&p_wv,  c_wv);
    cudaGetSymbolAddress((void**)&p_wqb, c_wqb);
    cudaGetSymbolAddress((void**)&p_wkb, c_wkb);

    WConvArgs wa;
    const float* srcs[5] = { Wq, Wk, Wv, Wqb, Wkb };
    __half* dsts[5] = { p_wq, p_wk, p_wv, p_wqb, p_wkb };
    int lens[5] = { INNER * IMG_DIM / 8, INNER * TXT_DIM / 8, INNER * TXT_DIM / 8,
                    3 * INNER * IMG_DIM / 8, 3 * INNER * TXT_DIM / 8 };
    int accum = 0;
    for (int i = 0; i < 5; i++) {
        wa.src[i] = srcs[i];
        wa.dst[i] = dsts[i];
        accum += lens[i];
        wa.end[i] = accum;
    }
    wconvert_kernel<<<1184, 256>>>(wa);

    hmma_gemm<<<dim3(GRID_X, 4), 256, SMEM_TOTAL>>>(out);
}

// round 10
// speedup vs baseline: 1.6968x; 1.6968x over previous
#include <cuda_runtime.h>
#include <cuda_fp16.h>
#include <cstdint>

// ---------------------------------------------------------------------------
// DynamicProjectionModule via pure-fp16 mma.sync (arch-portable; tcgen05 is
// rejected by the harness's plain compute_103 PTX pass).
//
// Accuracy: A and B rounded to fp16, fp32 accumulation -> rel_err 2.9e-4
// (measured), 3.4x under the 1e-3 gate.
//
// Round 10 == round 9 resubmitted after an infra flake: the router's fp64
// accumulation (~200us on GB300's cut-down FP64 pipe -- the hidden overhead
// in every prior round) is replaced by Kahan + TwoProd-FMA fp32 (error
// ~1e-6 abs vs score scale ~1.5), with a warp-level TRUE-fp64 recompute only
// when the top-2 margin < 1e-2 (~0.3% of tokens). Argmax fidelity vs jax
// fp32 scores is preserved.
// ---------------------------------------------------------------------------

#define BSZ      8
#define SEQ      1024
#define IMG_DIM  1024
#define TXT_DIM  768
#define INNER    1024
#define MROWS    (BSZ * SEQ)
#define TELEMS   ((long long)MROWS * INNER)

// ---- device scratch --------------------------------------------------------
__device__ int g_cnt[6];
__device__ int g_list[6][MROWS];

__device__ __half c_img[MROWS * IMG_DIM];
__device__ __half c_txt[MROWS * TXT_DIM];
__device__ __half c_wq [INNER * IMG_DIM];
__device__ __half c_wk [INNER * TXT_DIM];
__device__ __half c_wv [INNER * TXT_DIM];
__device__ __half c_wqb[3 * INNER * IMG_DIM];
__device__ __half c_wkb[3 * INNER * TXT_DIM];

// ---- helpers ---------------------------------------------------------------
__device__ __forceinline__ uint32_t smem_u32(const void* p) {
    uint32_t a;
    asm("{ .reg .u64 t; cvta.to.shared.u64 t, %1; cvt.u32.u64 %0, t; }" : "=r"(a) : "l"(p));
    return a;
}
__device__ __forceinline__ void cp16(uint32_t d, const void* g) {
    asm volatile("cp.async.cg.shared.global [%0], [%1], 16;" :: "r"(d), "l"(g));
}
__device__ __forceinline__ void cp_commit() { asm volatile("cp.async.commit_group;" ::: "memory"); }
template<int N> __device__ __forceinline__ void cp_wait() {
    asm volatile("cp.async.wait_group %0;" :: "n"(N) : "memory");
}
__device__ __forceinline__ void ldsm_x4(uint32_t& r0, uint32_t& r1, uint32_t& r2, uint32_t& r3,
                                        uint32_t addr) {
    asm volatile("ldmatrix.sync.aligned.m8n8.x4.shared.b16 {%0,%1,%2,%3}, [%4];"
                 : "=r"(r0), "=r"(r1), "=r"(r2), "=r"(r3) : "r"(addr));
}
__device__ __forceinline__ void mma16816(float* c, const uint32_t* a, const uint32_t* b) {
    asm volatile("mma.sync.aligned.m16n8k16.row.col.f32.f16.f16.f32 "
                 "{%0,%1,%2,%3}, {%4,%5,%6,%7}, {%8,%9}, {%0,%1,%2,%3};"
                 : "+f"(c[0]), "+f"(c[1]), "+f"(c[2]), "+f"(c[3])
                 : "r"(a[0]), "r"(a[1]), "r"(a[2]), "r"(a[3]), "r"(b[0]), "r"(b[1]));
}
#define SWZ(x) ((x) ^ (((x) >> 3) & 0x70))

// Kahan + TwoProd accumulate: (s, c) += x*w exactly to ~2 ulps.
// __f*_rn intrinsics are never re-associated/contracted by the compiler.
__device__ __forceinline__ void kacc(float x, float w, float& s, float& c) {
    float p = __fmul_rn(x, w);
    float e = __fmaf_rn(x, w, -p);         // exact product residual
    float t = __fadd_rn(s, p);
    float z = __fsub_rn(t, s);
    float g = __fadd_rn(__fsub_rn(s, __fsub_rn(t, z)), __fsub_rn(p, z));
    c = __fadd_rn(c, __fadd_rn(g, e));
    s = t;
}
// Merge (so, co) into (s, c) with TwoSum.
__device__ __forceinline__ void kmerge(float so, float co, float& s, float& c) {
    float t = __fadd_rn(s, so);
    float z = __fsub_rn(t, s);
    float g = __fadd_rn(__fsub_rn(s, __fsub_rn(t, z)), __fsub_rn(so, z));
    c = __fadd_rn(c, __fadd_rn(g, co));
    s = t;
}

// ---- setup -----------------------------------------------------------------
__global__ void init_kernel() {
    if (threadIdx.x < 6) g_cnt[threadIdx.x] = 0;
}

// Fused routing + fp32->fp16 activation convert. One warp per token row.
// Scores via Kahan fp32; fp64 warp recompute iff top-2 margin < 1e-2.
__global__ void route_conv_kernel(const float* __restrict__ img,
                                  const float* __restrict__ txt,
                                  const float* __restrict__ Wrq,
                                  const float* __restrict__ Wrk) {
    int warp = (blockIdx.x * blockDim.x + threadIdx.x) >> 5;
    int lane = threadIdx.x & 31;
    int side = blockIdx.y;
    if (warp >= MROWS) return;

    const float* x;  const float* wr;  __half* y;  int dim;
    if (side == 0) { x = img + (size_t)warp * IMG_DIM; wr = Wrq;
                     y = c_img + (size_t)warp * IMG_DIM; dim = IMG_DIM; }
    else           { x = txt + (size_t)warp * TXT_DIM; wr = Wrk;
                     y = c_txt + (size_t)warp * TXT_DIM; dim = TXT_DIM; }

    float s0 = 0.f, s1 = 0.f, s2 = 0.f, e0 = 0.f, e1 = 0.f, e2 = 0.f;
    for (int k0 = 0; k0 < dim; k0 += 128) {
        int k = k0 + lane * 4;
        float4 xv = *reinterpret_cast<const float4*>(x + k);

        __half2 h0 = __floats2half2_rn(xv.x, xv.y);
        __half2 h1 = __floats2half2_rn(xv.z, xv.w);
        uint2 o;
        o.x = *reinterpret_cast<uint32_t*>(&h0);
        o.y = *reinterpret_cast<uint32_t*>(&h1);
        *reinterpret_cast<uint2*>(y + k) = o;

        float4 w0 = *reinterpret_cast<const float4*>(wr + k);
        float4 w1 = *reinterpret_cast<const float4*>(wr + dim + k);
        float4 w2 = *reinterpret_cast<const float4*>(wr + 2 * dim + k);
        kacc(xv.x, w0.x, s0, e0); kacc(xv.y, w0.y, s0, e0);
        kacc(xv.z, w0.z, s0, e0); kacc(xv.w, w0.w, s0, e0);
        kacc(xv.x, w1.x, s1, e1); kacc(xv.y, w1.y, s1, e1);
        kacc(xv.z, w1.z, s1, e1); kacc(xv.w, w1.w, s1, e1);
        kacc(xv.x, w2.x, s2, e2); kacc(xv.y, w2.y, s2, e2);
        kacc(xv.z, w2.z, s2, e2); kacc(xv.w, w2.w, s2, e2);
    }
    #pragma unroll
    for (int off = 16; off; off >>= 1) {
        float a, b;
        a = __shfl_down_sync(0xffffffffu, s0, off);
        b = __shfl_down_sync(0xffffffffu, e0, off);
        kmerge(a, b, s0, e0);
        a = __shfl_down_sync(0xffffffffu, s1, off);
        b = __shfl_down_sync(0xffffffffu, e1, off);
        kmerge(a, b, s1, e1);
        a = __shfl_down_sync(0xffffffffu, s2, off);
        b = __shfl_down_sync(0xffffffffu, e2, off);
        kmerge(a, b, s2, e2);
    }

    double v0 = 0, v1 = 0, v2 = 0;
    int need64 = 0;
    if (lane == 0) {
        v0 = (double)s0 + (double)e0;
        v1 = (double)s1 + (double)e1;
        v2 = (double)s2 + (double)e2;
        double hi = v0 > v1 ? (v0 > v2 ? v0 : v2) : (v1 > v2 ? v1 : v2);
        double mid = v0 + v1 + v2
                   - hi
                   - (v0 < v1 ? (v0 < v2 ? v0 : v2) : (v1 < v2 ? v1 : v2));
        need64 = (hi - mid) < 1e-2;
    }
    need64 = __shfl_sync(0xffffffffu, need64, 0);

    if (need64) {   // rare (~0.3% of tokens): exact fp64 recompute, warp-wide
        double d0 = 0, d1 = 0, d2 = 0;
        for (int k = lane; k < dim; k += 32) {
            double xv = (double)x[k];
            d0 += xv * (double)wr[k];
            d1 += xv * (double)wr[dim + k];
            d2 += xv * (double)wr[2 * dim + k];
        }
        #pragma unroll
        for (int off = 16; off; off >>= 1) {
            d0 += __shfl_down_sync(0xffffffffu, d0, off);
            d1 += __shfl_down_sync(0xffffffffu, d1, off);
            d2 += __shfl_down_sync(0xffffffffu, d2, off);
        }
        if (lane == 0) { v0 = d0; v1 = d1; v2 = d2; }
    }

    if (lane == 0) {
        int p = 0; double best = v0;
        if (v1 > best) { best = v1; p = 1; }
        if (v2 > best) { best = v2; p = 2; }
        int pos = atomicAdd(&g_cnt[side * 3 + p], 1);
        g_list[side * 3 + p][pos] = warp;
    }
}

// Fused fp32 -> fp16 cast over the 5 weight tensors, 8 elem/unit.
struct WConvArgs {
    const float* src[5];
    __half*      dst[5];
    int          end[5];
};
__global__ void wconvert_kernel(WConvArgs a) {
    const int total = a.end[4];
    const int stride = gridDim.x * blockDim.x;
    for (int i = blockIdx.x * blockDim.x + threadIdx.x; i < total; i += stride) {
        int s = 0;
        #pragma unroll
        for (int t = 0; t < 4; t++) s += (i >= a.end[t]);
        int j = i - (s ? a.end[s - 1] : 0);
        const float4* p = reinterpret_cast<const float4*>(a.src[s]) + 2 * (size_t)j;
        float4 x = p[0], y = p[1];
        __half2 h0 = __floats2half2_rn(x.x, x.y);
        __half2 h1 = __floats2half2_rn(x.z, x.w);
        __half2 h2 = __floats2half2_rn(y.x, y.y);
        __half2 h3 = __floats2half2_rn(y.z, y.w);
        uint4 o;
        o.x = *reinterpret_cast<uint32_t*>(&h0);
        o.y = *reinterpret_cast<uint32_t*>(&h1);
        o.z = *reinterpret_cast<uint32_t*>(&h2);
        o.w = *reinterpret_cast<uint32_t*>(&h3);
        reinterpret_cast<uint4*>(a.dst[s])[j] = o;
    }
}

// ---- fused HMMA GEMM -------------------------------------------------------
// CTA tile 128(M) x 256(N), K-chunk 64, 3-stage cp.async, SW128 swizzle.
// 8 warps as 2(M) x 4(N); warp tile 64x64.  grid = (324, 4).
#define KC        64
#define A_BYTES   (128 * 128)
#define B_BYTES   (256 * 128)
#define STG_BYTES (A_BYTES + B_BYTES)
#define STAGES    3
#define CTRL_OFF  (STAGES * STG_BYTES)    /* 144 KB */
#define SMEM_TOTAL (CTRL_OFF + 512)
#define GRID_X    324

__global__ void __launch_bounds__(256, 1)
hmma_gemm(float* __restrict__ out)
{
    extern __shared__ char smem[];
    const int bx = blockIdx.x;

    const __half* A;  const __half* W;
    long long outBase;  int K, slot, rowBase;

    if (bx < 192) {
        int g = bx >> 6, t = bx & 63;
        rowBase = t * 128;  slot = -1;
        if (g == 0)      { A = c_img; W = c_wq; outBase = 0;          K = IMG_DIM; }
        else if (g == 1) { A = c_txt; W = c_wk; outBase = TELEMS;     K = TXT_DIM; }
        else             { A = c_txt; W = c_wv; outBase = 2 * TELEMS; K = TXT_DIM; }
    } else if (bx < 258) {
        int t = bx - 192;
        int c0 = (g_cnt[0] + 127) >> 7, c1 = (g_cnt[1] + 127) >> 7,
            c2 = (g_cnt[2] + 127) >> 7;
        int p, loc;
        if (t < c0)            { p = 0; loc = t; }
        else if (t < c0 + c1)  { p = 1; loc = t - c0; }
        else if (t < c0 + c1 + c2) { p = 2; loc = t - c0 - c1; }
        else return;
        A = c_img;  W = c_wqb + (size_t)p * INNER * IMG_DIM;
        outBase = 3 * TELEMS;  K = IMG_DIM;  slot = p;  rowBase = loc * 128;
    } else {
        int t = bx - 258;
        int c0 = (g_cnt[3] + 127) >> 7, c1 = (g_cnt[4] + 127) >> 7,
            c2 = (g_cnt[5] + 127) >> 7;
        int p, loc;
        if (t < c0)            { p = 0; loc = t; }
        else if (t < c0 + c1)  { p = 1; loc = t - c0; }
        else if (t < c0 + c1 + c2) { p = 2; loc = t - c0 - c1; }
        else return;
        A = c_txt;  W = c_wkb + (size_t)p * INNER * TXT_DIM;
        outBase = 4 * TELEMS;  K = TXT_DIM;  slot = 3 + p;  rowBase = loc * 128;
    }

    const int NCHUNK = K / KC;
    const int colBase = blockIdx.y * 256;
    const int cnt = (slot >= 0) ? g_cnt[slot] : MROWS;

    const int tid  = threadIdx.x;
    const int wid  = tid >> 5;
    const int lane = tid & 31;

    const uint32_t sb = smem_u32(smem);
    int* s_rowmap = (int*)(smem + CTRL_OFF);
    if (tid < 128) {
        int gr = rowBase + tid;
        s_rowmap[tid] = (slot < 0) ? gr : ((gr < cnt) ? g_list[slot][gr] : 0);
    }
    __syncthreads();

    const int wm = (wid & 1) * 64;
    const int wn = (wid >> 1) * 64;

    auto load_stage = [&](int buf, int chunk) {
        const int kc = chunk * KC;
        const uint32_t base = sb + buf * STG_BYTES;
        #pragma unroll
        for (int j = 0; j < 4; j++) {
            int t = tid + j * 256;
            int r = t >> 3, c = t & 7;
            const __half* g = A + (size_t)s_rowmap[r] * K + kc + c * 8;
            cp16(base + SWZ(r * 128 + c * 16), g);
        }
        #pragma unroll
        for (int j = 0; j < 8; j++) {
            int t = tid + j * 256;
            int r = t >> 3, c = t & 7;
            const __half* g = W + (size_t)(colBase + r) * K + kc + c * 8;
            cp16(base + A_BYTES + SWZ(r * 128 + c * 16), g);
        }
    };

    float acc[4][8][4];
    #pragma unroll
    for (int m = 0; m < 4; m++)
        #pragma unroll
        for (int n = 0; n < 8; n++)
            #pragma unroll
            for (int q = 0; q < 4; q++) acc[m][n][q] = 0.f;

    load_stage(0, 0); cp_commit();
    load_stage(1, 1); cp_commit();

    for (int c = 0; c < NCHUNK; c++) {
        const int buf = c % STAGES;
        cp_wait<STAGES - 2>();
        __syncthreads();

        if (c + 2 < NCHUNK) load_stage((c + 2) % STAGES, c + 2);
        cp_commit();

        const uint32_t aB = sb + buf * STG_BYTES;
        const uint32_t bB = aB + A_BYTES;

        #pragma unroll
        for (int ks = 0; ks < 4; ks++) {
            uint32_t a[4][4];
            #pragma unroll
            for (int m = 0; m < 4; m++) {
                int row = wm + m * 16 + (lane & 15);
                int c16 = ks * 2 + (lane >> 4);
                ldsm_x4(a[m][0], a[m][1], a[m][2], a[m][3],
                        aB + SWZ(row * 128 + c16 * 16));
            }
            uint32_t b[8][2];
            #pragma unroll
            for (int t = 0; t < 4; t++) {
                int nrow = wn + t * 16 + (lane & 7) + ((lane >> 4) << 3);
                int c16  = ks * 2 + ((lane >> 3) & 1);
                uint32_t r0, r1, r2, r3;
                ldsm_x4(r0, r1, r2, r3, bB + SWZ(nrow * 128 + c16 * 16));
                b[2 * t][0] = r0;     b[2 * t][1] = r1;
                b[2 * t + 1][0] = r2; b[2 * t + 1][1] = r3;
            }
            #pragma unroll
            for (int m = 0; m < 4; m++)
                #pragma unroll
                for (int n = 0; n < 8; n++)
                    mma16816(acc[m][n], a[m], b[n]);
        }
        __syncthreads();
    }

    const int head = (colBase + wn) >> 6;
    #pragma unroll
    for (int m = 0; m < 4; m++) {
        #pragma unroll
        for (int half = 0; half < 2; half++) {
            int rr = wm + m * 16 + (lane >> 2) + half * 8;
            if (rowBase + rr >= cnt) continue;
            int mt = s_rowmap[rr];
            int bb = mt >> 10, sq = mt & 1023;
            long long off0 = outBase + (((long long)(bb * 16 + head) * 1024 + sq) * 64);
            #pragma unroll
            for (int n = 0; n < 8; n++) {
                int dd = n * 8 + 2 * (lane & 3);
                float2 v = make_float2(acc[m][n][half * 2], acc[m][n][half * 2 + 1]);
                *reinterpret_cast<float2*>(out + off0 + dd) = v;
            }
        }
    }
}

// ---- host ------------------------------------------------------------------
extern "C" void kernel_launch(void* const* d_in, const int* in_sizes, int n_in,
                              void* d_out, int out_size) {
    (void)in_sizes; (void)n_in; (void)out_size;
    const float* img = (const float*)d_in[0];
    const float* txt = (const float*)d_in[1];
    const float* Wq  = (const float*)d_in[2];
    const float* Wk  = (const float*)d_in[3];
    const float* Wv  = (const float*)d_in[4];
    const float* Wqb = (const float*)d_in[5];
    const float* Wkb = (const float*)d_in[6];
    const float* Wrq = (const float*)d_in[7];
    const float* Wrk = (const float*)d_in[8];
    float* out = (float*)d_out;

    cudaFuncSetAttribute(hmma_gemm, cudaFuncAttributeMaxDynamicSharedMemorySize,
                         SMEM_TOTAL);

    init_kernel<<<1, 32>>>();
    route_conv_kernel<<<dim3(1024, 2), 256>>>(img, txt, Wrq, Wrk);

    __half *p_wq, *p_wk, *p_wv, *p_wqb, *p_wkb;
    cudaGetSymbolAddress((void**)&p_wq,  c_wq);
    cudaGetSymbolAddress((void**)&p_wk,  c_wk);
    cudaGetSymbolAddress((void**)&p_wv,  c_wv);
    cudaGetSymbolAddress((void**)&p_wqb, c_wqb);
    cudaGetSymbolAddress((void**)&p_wkb, c_wkb);

    WConvArgs wa;
    const float* srcs[5] = { Wq, Wk, Wv, Wqb, Wkb };
    __half* dsts[5] = { p_wq, p_wk, p_wv, p_wqb, p_wkb };
    int lens[5] = { INNER * IMG_DIM / 8, INNER * TXT_DIM / 8, INNER * TXT_DIM / 8,
                    3 * INNER * IMG_DIM / 8, 3 * INNER * TXT_DIM / 8 };
    int accum = 0;
    for (int i = 0; i < 5; i++) {
        wa.src[i] = srcs[i];
        wa.dst[i] = dsts[i];
        accum += lens[i];
        wa.end[i] = accum;
    }
    wconvert_kernel<<<1184, 256>>>(wa);

    hmma_gemm<<<dim3(GRID_X, 4), 256, SMEM_TOTAL>>>(out);
}

// round 11
// speedup vs baseline: 2.3875x; 1.4071x over previous
#include <cuda_runtime.h>
#include <cuda_fp16.h>
#include <cstdint>

// ---------------------------------------------------------------------------
// DynamicProjectionModule via fp16 tensor-core GEMM.
//
// Round 11 experiment: the GEMM kernel body is compiled two ways.
//  - plain compute_103 pass: the proven mma.sync HMMA body (336 TF/s, at the
//    legacy-pipe HW ceiling) -- byte-identical fallback.
//  - IF the harness also runs an sm_103a-featured pass
//    (__CUDA_ARCH_FEAT_SM103_ALL defined), that cubin gets a tcgen05 SS
//    kind::f16 GEMM (TMEM accumulators), reusing the exact same fp16 inputs,
//    tiles (128x256), cp.async staging, and epilogue layout.
// Router: Kahan fp32 + rare fp64 fallback (round 10, confirmed -190us).
// ---------------------------------------------------------------------------

#define BSZ      8
#define SEQ      1024
#define IMG_DIM  1024
#define TXT_DIM  768
#define INNER    1024
#define MROWS    (BSZ * SEQ)
#define TELEMS   ((long long)MROWS * INNER)

// ---- device scratch --------------------------------------------------------
__device__ int g_cnt[6];
__device__ int g_list[6][MROWS];

__device__ __half c_img[MROWS * IMG_DIM];
__device__ __half c_txt[MROWS * TXT_DIM];
__device__ __half c_wq [INNER * IMG_DIM];
__device__ __half c_wk [INNER * TXT_DIM];
__device__ __half c_wv [INNER * TXT_DIM];
__device__ __half c_wqb[3 * INNER * IMG_DIM];
__device__ __half c_wkb[3 * INNER * TXT_DIM];

// ---- helpers ---------------------------------------------------------------
__device__ __forceinline__ uint32_t smem_u32(const void* p) {
    uint32_t a;
    asm("{ .reg .u64 t; cvta.to.shared.u64 t, %1; cvt.u32.u64 %0, t; }" : "=r"(a) : "l"(p));
    return a;
}
__device__ __forceinline__ void cp16(uint32_t d, const void* g) {
    asm volatile("cp.async.cg.shared.global [%0], [%1], 16;" :: "r"(d), "l"(g));
}
__device__ __forceinline__ void cp_commit() { asm volatile("cp.async.commit_group;" ::: "memory"); }
template<int N> __device__ __forceinline__ void cp_wait() {
    asm volatile("cp.async.wait_group %0;" :: "n"(N) : "memory");
}
__device__ __forceinline__ void ldsm_x4(uint32_t& r0, uint32_t& r1, uint32_t& r2, uint32_t& r3,
                                        uint32_t addr) {
    asm volatile("ldmatrix.sync.aligned.m8n8.x4.shared.b16 {%0,%1,%2,%3}, [%4];"
                 : "=r"(r0), "=r"(r1), "=r"(r2), "=r"(r3) : "r"(addr));
}
__device__ __forceinline__ void mma16816(float* c, const uint32_t* a, const uint32_t* b) {
    asm volatile("mma.sync.aligned.m16n8k16.row.col.f32.f16.f16.f32 "
                 "{%0,%1,%2,%3}, {%4,%5,%6,%7}, {%8,%9}, {%0,%1,%2,%3};"
                 : "+f"(c[0]), "+f"(c[1]), "+f"(c[2]), "+f"(c[3])
                 : "r"(a[0]), "r"(a[1]), "r"(a[2]), "r"(a[3]), "r"(b[0]), "r"(b[1]));
}
#define SWZ(x) ((x) ^ (((x) >> 3) & 0x70))

#if defined(__CUDA_ARCH_FEAT_SM103_ALL)
// ---- tcgen05 helpers (only in the sm_103a-featured pass) -------------------
__device__ __forceinline__ void fence_gen_to_async() {
    asm volatile("fence.proxy.async.shared::cta;" ::: "memory");
}
__device__ __forceinline__ void mbar_init(uint32_t a, uint32_t c) {
    asm volatile("mbarrier.init.shared.b64 [%0], %1;" :: "r"(a), "r"(c) : "memory");
}
__device__ __forceinline__ void mbar_wait(uint32_t a, uint32_t parity) {
    asm volatile(
        "{\n\t.reg .pred P;\n\t"
        "W_%=:\n\t"
        "mbarrier.try_wait.parity.acquire.cta.shared::cta.b64 P, [%0], %1, 0x989680;\n\t"
        "@!P bra W_%=;\n\t}"
        :: "r"(a), "r"(parity) : "memory");
}
__device__ __forceinline__ void tc_commit(uint32_t mbar) {
    asm volatile(
        "tcgen05.commit.cta_group::1.mbarrier::arrive::one.shared::cluster.b64 [%0];"
        :: "r"(mbar) : "memory");
}
__device__ __forceinline__ void tc_alloc(uint32_t smem_dst, uint32_t ncols) {
    asm volatile("tcgen05.alloc.cta_group::1.sync.aligned.shared::cta.b32 [%0], %1;"
                 :: "r"(smem_dst), "r"(ncols) : "memory");
}
__device__ __forceinline__ void tc_dealloc(uint32_t tmem, uint32_t ncols) {
    asm volatile("tcgen05.dealloc.cta_group::1.sync.aligned.b32 %0, %1;" :: "r"(tmem), "r"(ncols));
}
__device__ __forceinline__ void tc_relinquish() {
    asm volatile("tcgen05.relinquish_alloc_permit.cta_group::1.sync.aligned;");
}
__device__ __forceinline__ void tc_fence_after() {
    asm volatile("tcgen05.fence::after_thread_sync;" ::: "memory");
}
__device__ __forceinline__ void tc_fence_before() {
    asm volatile("tcgen05.fence::before_thread_sync;" ::: "memory");
}
__device__ __forceinline__ void tc_wait_ld() {
    asm volatile("tcgen05.wait::ld.sync.aligned;" ::: "memory");
}
__device__ __forceinline__ void mma_f16_ss(uint32_t d_tmem, uint64_t a_desc, uint64_t b_desc,
                                           uint32_t idesc, bool accum) {
    uint32_t en = accum ? 1u : 0u;
    asm volatile(
        "{\n\t.reg .pred p;\n\t"
        "setp.ne.u32 p, %4, 0;\n\t"
        "tcgen05.mma.cta_group::1.kind::f16 [%0], %1, %2, %3, {%5, %5, %5, %5}, p;\n\t}"
        :: "r"(d_tmem), "l"(a_desc), "l"(b_desc), "r"(idesc), "r"(en), "r"(0u)
        : "memory");
}
#define TC_LD_X32(r, addr)                                                     \
    asm volatile("tcgen05.ld.sync.aligned.32x32b.x32.b32 "                     \
        "{%0,%1,%2,%3,%4,%5,%6,%7,%8,%9,%10,%11,%12,%13,%14,%15,"              \
        "%16,%17,%18,%19,%20,%21,%22,%23,%24,%25,%26,%27,%28,%29,%30,%31}, [%32];" \
        : "=r"((r)[0]),"=r"((r)[1]),"=r"((r)[2]),"=r"((r)[3]),                 \
          "=r"((r)[4]),"=r"((r)[5]),"=r"((r)[6]),"=r"((r)[7]),                 \
          "=r"((r)[8]),"=r"((r)[9]),"=r"((r)[10]),"=r"((r)[11]),               \
          "=r"((r)[12]),"=r"((r)[13]),"=r"((r)[14]),"=r"((r)[15]),             \
          "=r"((r)[16]),"=r"((r)[17]),"=r"((r)[18]),"=r"((r)[19]),             \
          "=r"((r)[20]),"=r"((r)[21]),"=r"((r)[22]),"=r"((r)[23]),             \
          "=r"((r)[24]),"=r"((r)[25]),"=r"((r)[26]),"=r"((r)[27]),             \
          "=r"((r)[28]),"=r"((r)[29]),"=r"((r)[30]),"=r"((r)[31])              \
        : "r"(addr))
// SW128 descriptor (layout=2, version=1, SBO=64, LBO=1)
static __device__ __forceinline__ uint64_t make_desc(uint32_t addr) {
    return (uint64_t(2) << 61) | (uint64_t(1) << 46) | (uint64_t(64) << 32)
         | (uint64_t(1) << 16) | ((uint64_t)(addr >> 4) & 0x3FFF);
}
// idesc: dtype F32, atype=btype=F16 (0), N=256, M=128
#define TC_IDESC ((1u << 4) | (32u << 17) | (8u << 24))
#endif  // __CUDA_ARCH_FEAT_SM103_ALL

// Kahan + TwoProd accumulate: (s, c) += x*w exactly to ~2 ulps.
__device__ __forceinline__ void kacc(float x, float w, float& s, float& c) {
    float p = __fmul_rn(x, w);
    float e = __fmaf_rn(x, w, -p);
    float t = __fadd_rn(s, p);
    float z = __fsub_rn(t, s);
    float g = __fadd_rn(__fsub_rn(s, __fsub_rn(t, z)), __fsub_rn(p, z));
    c = __fadd_rn(c, __fadd_rn(g, e));
    s = t;
}
__device__ __forceinline__ void kmerge(float so, float co, float& s, float& c) {
    float t = __fadd_rn(s, so);
    float z = __fsub_rn(t, s);
    float g = __fadd_rn(__fsub_rn(s, __fsub_rn(t, z)), __fsub_rn(so, z));
    c = __fadd_rn(c, __fadd_rn(g, co));
    s = t;
}

// ---- setup -----------------------------------------------------------------
__global__ void init_kernel() {
    if (threadIdx.x < 6) g_cnt[threadIdx.x] = 0;
}

// Fused routing + fp32->fp16 activation convert (round 10, proven).
__global__ void route_conv_kernel(const float* __restrict__ img,
                                  const float* __restrict__ txt,
                                  const float* __restrict__ Wrq,
                                  const float* __restrict__ Wrk) {
    int warp = (blockIdx.x * blockDim.x + threadIdx.x) >> 5;
    int lane = threadIdx.x & 31;
    int side = blockIdx.y;
    if (warp >= MROWS) return;

    const float* x;  const float* wr;  __half* y;  int dim;
    if (side == 0) { x = img + (size_t)warp * IMG_DIM; wr = Wrq;
                     y = c_img + (size_t)warp * IMG_DIM; dim = IMG_DIM; }
    else           { x = txt + (size_t)warp * TXT_DIM; wr = Wrk;
                     y = c_txt + (size_t)warp * TXT_DIM; dim = TXT_DIM; }

    float s0 = 0.f, s1 = 0.f, s2 = 0.f, e0 = 0.f, e1 = 0.f, e2 = 0.f;
    for (int k0 = 0; k0 < dim; k0 += 128) {
        int k = k0 + lane * 4;
        float4 xv = *reinterpret_cast<const float4*>(x + k);

        __half2 h0 = __floats2half2_rn(xv.x, xv.y);
        __half2 h1 = __floats2half2_rn(xv.z, xv.w);
        uint2 o;
        o.x = *reinterpret_cast<uint32_t*>(&h0);
        o.y = *reinterpret_cast<uint32_t*>(&h1);
        *reinterpret_cast<uint2*>(y + k) = o;

        float4 w0 = *reinterpret_cast<const float4*>(wr + k);
        float4 w1 = *reinterpret_cast<const float4*>(wr + dim + k);
        float4 w2 = *reinterpret_cast<const float4*>(wr + 2 * dim + k);
        kacc(xv.x, w0.x, s0, e0); kacc(xv.y, w0.y, s0, e0);
        kacc(xv.z, w0.z, s0, e0); kacc(xv.w, w0.w, s0, e0);
        kacc(xv.x, w1.x, s1, e1); kacc(xv.y, w1.y, s1, e1);
        kacc(xv.z, w1.z, s1, e1); kacc(xv.w, w1.w, s1, e1);
        kacc(xv.x, w2.x, s2, e2); kacc(xv.y, w2.y, s2, e2);
        kacc(xv.z, w2.z, s2, e2); kacc(xv.w, w2.w, s2, e2);
    }
    #pragma unroll
    for (int off = 16; off; off >>= 1) {
        float a, b;
        a = __shfl_down_sync(0xffffffffu, s0, off);
        b = __shfl_down_sync(0xffffffffu, e0, off);
        kmerge(a, b, s0, e0);
        a = __shfl_down_sync(0xffffffffu, s1, off);
        b = __shfl_down_sync(0xffffffffu, e1, off);
        kmerge(a, b, s1, e1);
        a = __shfl_down_sync(0xffffffffu, s2, off);
        b = __shfl_down_sync(0xffffffffu, e2, off);
        kmerge(a, b, s2, e2);
    }

    double v0 = 0, v1 = 0, v2 = 0;
    int need64 = 0;
    if (lane == 0) {
        v0 = (double)s0 + (double)e0;
        v1 = (double)s1 + (double)e1;
        v2 = (double)s2 + (double)e2;
        double hi = v0 > v1 ? (v0 > v2 ? v0 : v2) : (v1 > v2 ? v1 : v2);
        double mid = v0 + v1 + v2
                   - hi
                   - (v0 < v1 ? (v0 < v2 ? v0 : v2) : (v1 < v2 ? v1 : v2));
        need64 = (hi - mid) < 1e-2;
    }
    need64 = __shfl_sync(0xffffffffu, need64, 0);

    if (need64) {
        double d0 = 0, d1 = 0, d2 = 0;
        for (int k = lane; k < dim; k += 32) {
            double xv = (double)x[k];
            d0 += xv * (double)wr[k];
            d1 += xv * (double)wr[dim + k];
            d2 += xv * (double)wr[2 * dim + k];
        }
        #pragma unroll
        for (int off = 16; off; off >>= 1) {
            d0 += __shfl_down_sync(0xffffffffu, d0, off);
            d1 += __shfl_down_sync(0xffffffffu, d1, off);
            d2 += __shfl_down_sync(0xffffffffu, d2, off);
        }
        if (lane == 0) { v0 = d0; v1 = d1; v2 = d2; }
    }

    if (lane == 0) {
        int p = 0; double best = v0;
        if (v1 > best) { best = v1; p = 1; }
        if (v2 > best) { best = v2; p = 2; }
        int pos = atomicAdd(&g_cnt[side * 3 + p], 1);
        g_list[side * 3 + p][pos] = warp;
    }
}

// Fused fp32 -> fp16 cast over the 5 weight tensors, 8 elem/unit.
struct WConvArgs {
    const float* src[5];
    __half*      dst[5];
    int          end[5];
};
__global__ void wconvert_kernel(WConvArgs a) {
    const int total = a.end[4];
    const int stride = gridDim.x * blockDim.x;
    for (int i = blockIdx.x * blockDim.x + threadIdx.x; i < total; i += stride) {
        int s = 0;
        #pragma unroll
        for (int t = 0; t < 4; t++) s += (i >= a.end[t]);
        int j = i - (s ? a.end[s - 1] : 0);
        const float4* p = reinterpret_cast<const float4*>(a.src[s]) + 2 * (size_t)j;
        float4 x = p[0], y = p[1];
        __half2 h0 = __floats2half2_rn(x.x, x.y);
        __half2 h1 = __floats2half2_rn(x.z, x.w);
        __half2 h2 = __floats2half2_rn(y.x, y.y);
        __half2 h3 = __floats2half2_rn(y.z, y.w);
        uint4 o;
        o.x = *reinterpret_cast<uint32_t*>(&h0);
        o.y = *reinterpret_cast<uint32_t*>(&h1);
        o.z = *reinterpret_cast<uint32_t*>(&h2);
        o.w = *reinterpret_cast<uint32_t*>(&h3);
        reinterpret_cast<uint4*>(a.dst[s])[j] = o;
    }
}

// ---- fused GEMM ------------------------------------------------------------
// CTA tile 128(M) x 256(N), K-chunk 64, 3-stage cp.async, SW128 swizzle.
// grid = (324, 4); tile schedule decoded per-CTA from blockIdx + g_cnt.
#define KC        64
#define A_BYTES   (128 * 128)
#define B_BYTES   (256 * 128)
#define STG_BYTES (A_BYTES + B_BYTES)
#define STAGES    3
#define CTRL_OFF  (STAGES * STG_BYTES)    /* 144 KB */
#define SMEM_TOTAL (CTRL_OFF + 1024)
#define GRID_X    324

__global__ void __launch_bounds__(256, 1)
hmma_gemm(float* __restrict__ out)
{
    extern __shared__ char smem[];
    const int bx = blockIdx.x;

    const __half* A;  const __half* W;
    long long outBase;  int K, slot, rowBase;

    if (bx < 192) {
        int g = bx >> 6, t = bx & 63;
        rowBase = t * 128;  slot = -1;
        if (g == 0)      { A = c_img; W = c_wq; outBase = 0;          K = IMG_DIM; }
        else if (g == 1) { A = c_txt; W = c_wk; outBase = TELEMS;     K = TXT_DIM; }
        else             { A = c_txt; W = c_wv; outBase = 2 * TELEMS; K = TXT_DIM; }
    } else if (bx < 258) {
        int t = bx - 192;
        int c0 = (g_cnt[0] + 127) >> 7, c1 = (g_cnt[1] + 127) >> 7,
            c2 = (g_cnt[2] + 127) >> 7;
        int p, loc;
        if (t < c0)            { p = 0; loc = t; }
        else if (t < c0 + c1)  { p = 1; loc = t - c0; }
        else if (t < c0 + c1 + c2) { p = 2; loc = t - c0 - c1; }
        else return;
        A = c_img;  W = c_wqb + (size_t)p * INNER * IMG_DIM;
        outBase = 3 * TELEMS;  K = IMG_DIM;  slot = p;  rowBase = loc * 128;
    } else {
        int t = bx - 258;
        int c0 = (g_cnt[3] + 127) >> 7, c1 = (g_cnt[4] + 127) >> 7,
            c2 = (g_cnt[5] + 127) >> 7;
        int p, loc;
        if (t < c0)            { p = 0; loc = t; }
        else if (t < c0 + c1)  { p = 1; loc = t - c0; }
        else if (t < c0 + c1 + c2) { p = 2; loc = t - c0 - c1; }
        else return;
        A = c_txt;  W = c_wkb + (size_t)p * INNER * TXT_DIM;
        outBase = 4 * TELEMS;  K = TXT_DIM;  slot = 3 + p;  rowBase = loc * 128;
    }

    const int NCHUNK = K / KC;
    const int colBase = blockIdx.y * 256;
    const int cnt = (slot >= 0) ? g_cnt[slot] : MROWS;

    const int tid  = threadIdx.x;
    const int wid  = tid >> 5;
    const int lane = tid & 31;

    const uint32_t sb = smem_u32(smem);
    int* s_rowmap = (int*)(smem + CTRL_OFF);
    if (tid < 128) {
        int gr = rowBase + tid;
        s_rowmap[tid] = (slot < 0) ? gr : ((gr < cnt) ? g_list[slot][gr] : 0);
    }

    auto load_stage = [&](int buf, int chunk) {
        const int kc = chunk * KC;
        const uint32_t base = sb + buf * STG_BYTES;
        #pragma unroll
        for (int j = 0; j < 4; j++) {
            int t = tid + j * 256;
            int r = t >> 3, c = t & 7;
            const __half* g = A + (size_t)s_rowmap[r] * K + kc + c * 8;
            cp16(base + SWZ(r * 128 + c * 16), g);
        }
        #pragma unroll
        for (int j = 0; j < 8; j++) {
            int t = tid + j * 256;
            int r = t >> 3, c = t & 7;
            const __half* g = W + (size_t)(colBase + r) * K + kc + c * 8;
            cp16(base + A_BYTES + SWZ(r * 128 + c * 16), g);
        }
    };

#if defined(__CUDA_ARCH_FEAT_SM103_ALL)
    // ======================= tcgen05 path ===================================
    const uint32_t mbar0 = sb + CTRL_OFF + 512;
    const uint32_t tptr  = sb + CTRL_OFF + 576;
    if (tid == 0)
        for (int s = 0; s < STAGES; s++) mbar_init(mbar0 + 8 * s, 1);
    if (wid == 0) tc_alloc(tptr, 256);
    __syncthreads();

    uint32_t tmem;
    asm volatile("ld.shared.b32 %0, [%1];" : "=r"(tmem) : "r"(tptr));

    load_stage(0, 0); cp_commit();
    load_stage(1, 1); cp_commit();

    int ph[STAGES];
    #pragma unroll
    for (int s = 0; s < STAGES; s++) ph[s] = 0;

    for (int i = 0; i < NCHUNK; i++) {
        const int buf = i % STAGES;
        cp_wait<STAGES - 2>();
        fence_gen_to_async();
        __syncthreads();

        if (tid == 0) {
            uint64_t ad = make_desc(sb + buf * STG_BYTES);
            uint64_t bd = make_desc(sb + buf * STG_BYTES + A_BYTES);
            #pragma unroll
            for (int ks = 0; ks < 4; ks++)
                mma_f16_ss(tmem, ad + ks * 2, bd + ks * 2, TC_IDESC,
                           (i > 0) || (ks > 0));
            tc_commit(mbar0 + 8 * buf);
        }

        if (i + 2 < NCHUNK) {
            if (i >= 1) {
                int pb = (i - 1) % STAGES;
                mbar_wait(mbar0 + 8 * pb, ph[pb]);
                ph[pb] ^= 1;
            }
            load_stage((i + 2) % STAGES, i + 2);
        }
        cp_commit();
    }

    {
        int lb = (NCHUNK - 1) % STAGES;
        mbar_wait(mbar0 + 8 * lb, ph[lb]);
    }
    tc_fence_after();

    // epilogue: warp w -> rows (w&3)*32+lane, col group (w>>2)*128
    {
        const int sp  = wid & 3;
        const int grp = wid >> 2;
        const int row = sp * 32 + lane;
        const bool valid = (rowBase + row) < cnt;
        const int mt = s_rowmap[row];
        const int bb = mt >> 10, sq = mt & 1023;
        #pragma unroll
        for (int cc = 0; cc < 4; cc++) {
            const int c0 = grp * 128 + cc * 32;
            uint32_t r[32];
            TC_LD_X32(r, tmem + c0);
            tc_wait_ld();
            if (valid) {
                const int n0 = colBase + c0;
                const int h = n0 >> 6, d0 = n0 & 63;
                long long off = outBase + (((long long)(bb * 16 + h) * 1024 + sq) * 64) + d0;
                float4* p = reinterpret_cast<float4*>(out + off);
                #pragma unroll
                for (int q = 0; q < 8; q++)
                    p[q] = make_float4(__uint_as_float(r[4 * q + 0]),
                                       __uint_as_float(r[4 * q + 1]),
                                       __uint_as_float(r[4 * q + 2]),
                                       __uint_as_float(r[4 * q + 3]));
            }
        }
    }
    tc_fence_before();
    __syncthreads();
    if (wid == 0) {
        tc_relinquish();
        tc_dealloc(tmem, 256);
    }
#else
    // ======================= HMMA fallback (round 10, proven) ===============
    __syncthreads();

    const int wm = (wid & 1) * 64;
    const int wn = (wid >> 1) * 64;

    float acc[4][8][4];
    #pragma unroll
    for (int m = 0; m < 4; m++)
        #pragma unroll
        for (int n = 0; n < 8; n++)
            #pragma unroll
            for (int q = 0; q < 4; q++) acc[m][n][q] = 0.f;

    load_stage(0, 0); cp_commit();
    load_stage(1, 1); cp_commit();

    for (int c = 0; c < NCHUNK; c++) {
        const int buf = c % STAGES;
        cp_wait<STAGES - 2>();
        __syncthreads();

        if (c + 2 < NCHUNK) load_stage((c + 2) % STAGES, c + 2);
        cp_commit();

        const uint32_t aB = sb + buf * STG_BYTES;
        const uint32_t bB = aB + A_BYTES;

        #pragma unroll
        for (int ks = 0; ks < 4; ks++) {
            uint32_t a[4][4];
            #pragma unroll
            for (int m = 0; m < 4; m++) {
                int row = wm + m * 16 + (lane & 15);
                int c16 = ks * 2 + (lane >> 4);
                ldsm_x4(a[m][0], a[m][1], a[m][2], a[m][3],
                        aB + SWZ(row * 128 + c16 * 16));
            }
            uint32_t b[8][2];
            #pragma unroll
            for (int t = 0; t < 4; t++) {
                int nrow = wn + t * 16 + (lane & 7) + ((lane >> 4) << 3);
                int c16  = ks * 2 + ((lane >> 3) & 1);
                uint32_t r0, r1, r2, r3;
                ldsm_x4(r0, r1, r2, r3, bB + SWZ(nrow * 128 + c16 * 16));
                b[2 * t][0] = r0;     b[2 * t][1] = r1;
                b[2 * t + 1][0] = r2; b[2 * t + 1][1] = r3;
            }
            #pragma unroll
            for (int m = 0; m < 4; m++)
                #pragma unroll
                for (int n = 0; n < 8; n++)
                    mma16816(acc[m][n], a[m], b[n]);
        }
        __syncthreads();
    }

    const int head = (colBase + wn) >> 6;
    #pragma unroll
    for (int m = 0; m < 4; m++) {
        #pragma unroll
        for (int half = 0; half < 2; half++) {
            int rr = wm + m * 16 + (lane >> 2) + half * 8;
            if (rowBase + rr >= cnt) continue;
            int mt = s_rowmap[rr];
            int bb = mt >> 10, sq = mt & 1023;
            long long off0 = outBase + (((long long)(bb * 16 + head) * 1024 + sq) * 64);
            #pragma unroll
            for (int n = 0; n < 8; n++) {
                int dd = n * 8 + 2 * (lane & 3);
                float2 v = make_float2(acc[m][n][half * 2], acc[m][n][half * 2 + 1]);
                *reinterpret_cast<float2*>(out + off0 + dd) = v;
            }
        }
    }
#endif
}

// ---- host ------------------------------------------------------------------
extern "C" void kernel_launch(void* const* d_in, const int* in_sizes, int n_in,
                              void* d_out, int out_size) {
    (void)in_sizes; (void)n_in; (void)out_size;
    const float* img = (const float*)d_in[0];
    const float* txt = (const float*)d_in[1];
    const float* Wq  = (const float*)d_in[2];
    const float* Wk  = (const float*)d_in[3];
    const float* Wv  = (const float*)d_in[4];
    const float* Wqb = (const float*)d_in[5];
    const float* Wkb = (const float*)d_in[6];
    const float* Wrq = (const float*)d_in[7];
    const float* Wrk = (const float*)d_in[8];
    float* out = (float*)d_out;

    cudaFuncSetAttribute(hmma_gemm, cudaFuncAttributeMaxDynamicSharedMemorySize,
                         SMEM_TOTAL);

    init_kernel<<<1, 32>>>();
    route_conv_kernel<<<dim3(1024, 2), 256>>>(img, txt, Wrq, Wrk);

    __half *p_wq, *p_wk, *p_wv, *p_wqb, *p_wkb;
    cudaGetSymbolAddress((void**)&p_wq,  c_wq);
    cudaGetSymbolAddress((void**)&p_wk,  c_wk);
    cudaGetSymbolAddress((void**)&p_wv,  c_wv);
    cudaGetSymbolAddress((void**)&p_wqb, c_wqb);
    cudaGetSymbolAddress((void**)&p_wkb, c_wkb);

    WConvArgs wa;
    const float* srcs[5] = { Wq, Wk, Wv, Wqb, Wkb };
    __half* dsts[5] = { p_wq, p_wk, p_wv, p_wqb, p_wkb };
    int lens[5] = { INNER * IMG_DIM / 8, INNER * TXT_DIM / 8, INNER * TXT_DIM / 8,
                    3 * INNER * IMG_DIM / 8, 3 * INNER * TXT_DIM / 8 };
    int accum = 0;
    for (int i = 0; i < 5; i++) {
        wa.src[i] = srcs[i];
        wa.dst[i] = dsts[i];
        accum += lens[i];
        wa.end[i] = accum;
    }
    wconvert_kernel<<<1184, 256>>>(wa);

    hmma_gemm<<<dim3(GRID_X, 4), 256, SMEM_TOTAL>>>(out);
}

// round 13
// speedup vs baseline: 2.4105x; 1.0096x over previous
#include <cuda_runtime.h>
#include <cuda_fp16.h>
#include <cstdint>

// ---------------------------------------------------------------------------
// DynamicProjectionModule, tcgen05 GEMM (sm_103a-featured pass; proven live
// in round 11) with HMMA mma.sync fallback for the plain compute_103 pass.
//
// Round 13 == round 12 resubmitted after an infra flake:
// CTA tile 128x512 (full 512-col TMEM accumulator, two N=256 MMA dispatch
// groups), halving A-side L2 traffic (0.85 -> 0.64 GB) and doubling
// MAC/byte. Kc=64, 2-stage cp.async double buffer (160 KB smem).
// Router: Kahan fp32 + rare fp64 fallback (round 10, proven).
// ---------------------------------------------------------------------------

#define BSZ      8
#define SEQ      1024
#define IMG_DIM  1024
#define TXT_DIM  768
#define INNER    1024
#define MROWS    (BSZ * SEQ)
#define TELEMS   ((long long)MROWS * INNER)

// ---- device scratch --------------------------------------------------------
__device__ int g_cnt[6];
__device__ int g_list[6][MROWS];

__device__ __half c_img[MROWS * IMG_DIM];
__device__ __half c_txt[MROWS * TXT_DIM];
__device__ __half c_wq [INNER * IMG_DIM];
__device__ __half c_wk [INNER * TXT_DIM];
__device__ __half c_wv [INNER * TXT_DIM];
__device__ __half c_wqb[3 * INNER * IMG_DIM];
__device__ __half c_wkb[3 * INNER * TXT_DIM];

// ---- helpers ---------------------------------------------------------------
__device__ __forceinline__ uint32_t smem_u32(const void* p) {
    uint32_t a;
    asm("{ .reg .u64 t; cvta.to.shared.u64 t, %1; cvt.u32.u64 %0, t; }" : "=r"(a) : "l"(p));
    return a;
}
__device__ __forceinline__ void cp16(uint32_t d, const void* g) {
    asm volatile("cp.async.cg.shared.global [%0], [%1], 16;" :: "r"(d), "l"(g));
}
__device__ __forceinline__ void cp_commit() { asm volatile("cp.async.commit_group;" ::: "memory"); }
template<int N> __device__ __forceinline__ void cp_wait() {
    asm volatile("cp.async.wait_group %0;" :: "n"(N) : "memory");
}
__device__ __forceinline__ void ldsm_x4(uint32_t& r0, uint32_t& r1, uint32_t& r2, uint32_t& r3,
                                        uint32_t addr) {
    asm volatile("ldmatrix.sync.aligned.m8n8.x4.shared.b16 {%0,%1,%2,%3}, [%4];"
                 : "=r"(r0), "=r"(r1), "=r"(r2), "=r"(r3) : "r"(addr));
}
__device__ __forceinline__ void mma16816(float* c, const uint32_t* a, const uint32_t* b) {
    asm volatile("mma.sync.aligned.m16n8k16.row.col.f32.f16.f16.f32 "
                 "{%0,%1,%2,%3}, {%4,%5,%6,%7}, {%8,%9}, {%0,%1,%2,%3};"
                 : "+f"(c[0]), "+f"(c[1]), "+f"(c[2]), "+f"(c[3])
                 : "r"(a[0]), "r"(a[1]), "r"(a[2]), "r"(a[3]), "r"(b[0]), "r"(b[1]));
}
#define SWZ(x) ((x) ^ (((x) >> 3) & 0x70))

#if defined(__CUDA_ARCH_FEAT_SM103_ALL)
// ---- tcgen05 helpers (featured pass only) ----------------------------------
__device__ __forceinline__ void fence_gen_to_async() {
    asm volatile("fence.proxy.async.shared::cta;" ::: "memory");
}
__device__ __forceinline__ void mbar_init(uint32_t a, uint32_t c) {
    asm volatile("mbarrier.init.shared.b64 [%0], %1;" :: "r"(a), "r"(c) : "memory");
}
__device__ __forceinline__ void mbar_wait(uint32_t a, uint32_t parity) {
    asm volatile(
        "{\n\t.reg .pred P;\n\t"
        "W_%=:\n\t"
        "mbarrier.try_wait.parity.acquire.cta.shared::cta.b64 P, [%0], %1, 0x989680;\n\t"
        "@!P bra W_%=;\n\t}"
        :: "r"(a), "r"(parity) : "memory");
}
__device__ __forceinline__ void tc_commit(uint32_t mbar) {
    asm volatile(
        "tcgen05.commit.cta_group::1.mbarrier::arrive::one.shared::cluster.b64 [%0];"
        :: "r"(mbar) : "memory");
}
__device__ __forceinline__ void tc_alloc(uint32_t smem_dst, uint32_t ncols) {
    asm volatile("tcgen05.alloc.cta_group::1.sync.aligned.shared::cta.b32 [%0], %1;"
                 :: "r"(smem_dst), "r"(ncols) : "memory");
}
__device__ __forceinline__ void tc_dealloc(uint32_t tmem, uint32_t ncols) {
    asm volatile("tcgen05.dealloc.cta_group::1.sync.aligned.b32 %0, %1;" :: "r"(tmem), "r"(ncols));
}
__device__ __forceinline__ void tc_relinquish() {
    asm volatile("tcgen05.relinquish_alloc_permit.cta_group::1.sync.aligned;");
}
__device__ __forceinline__ void tc_fence_after() {
    asm volatile("tcgen05.fence::after_thread_sync;" ::: "memory");
}
__device__ __forceinline__ void tc_fence_before() {
    asm volatile("tcgen05.fence::before_thread_sync;" ::: "memory");
}
__device__ __forceinline__ void tc_wait_ld() {
    asm volatile("tcgen05.wait::ld.sync.aligned;" ::: "memory");
}
__device__ __forceinline__ void mma_f16_ss(uint32_t d_tmem, uint64_t a_desc, uint64_t b_desc,
                                           uint32_t idesc, bool accum) {
    uint32_t en = accum ? 1u : 0u;
    asm volatile(
        "{\n\t.reg .pred p;\n\t"
        "setp.ne.u32 p, %4, 0;\n\t"
        "tcgen05.mma.cta_group::1.kind::f16 [%0], %1, %2, %3, {%5, %5, %5, %5}, p;\n\t}"
        :: "r"(d_tmem), "l"(a_desc), "l"(b_desc), "r"(idesc), "r"(en), "r"(0u)
        : "memory");
}
#define TC_LD_X32(r, addr)                                                     \
    asm volatile("tcgen05.ld.sync.aligned.32x32b.x32.b32 "                     \
        "{%0,%1,%2,%3,%4,%5,%6,%7,%8,%9,%10,%11,%12,%13,%14,%15,"              \
        "%16,%17,%18,%19,%20,%21,%22,%23,%24,%25,%26,%27,%28,%29,%30,%31}, [%32];" \
        : "=r"((r)[0]),"=r"((r)[1]),"=r"((r)[2]),"=r"((r)[3]),                 \
          "=r"((r)[4]),"=r"((r)[5]),"=r"((r)[6]),"=r"((r)[7]),                 \
          "=r"((r)[8]),"=r"((r)[9]),"=r"((r)[10]),"=r"((r)[11]),               \
          "=r"((r)[12]),"=r"((r)[13]),"=r"((r)[14]),"=r"((r)[15]),             \
          "=r"((r)[16]),"=r"((r)[17]),"=r"((r)[18]),"=r"((r)[19]),             \
          "=r"((r)[20]),"=r"((r)[21]),"=r"((r)[22]),"=r"((r)[23]),             \
          "=r"((r)[24]),"=r"((r)[25]),"=r"((r)[26]),"=r"((r)[27]),             \
          "=r"((r)[28]),"=r"((r)[29]),"=r"((r)[30]),"=r"((r)[31])              \
        : "r"(addr))
static __device__ __forceinline__ uint64_t make_desc(uint32_t addr) {
    return (uint64_t(2) << 61) | (uint64_t(1) << 46) | (uint64_t(64) << 32)
         | (uint64_t(1) << 16) | ((uint64_t)(addr >> 4) & 0x3FFF);
}
// idesc: dtype F32, atype=btype=F16, N=256, M=128
#define TC_IDESC ((1u << 4) | (32u << 17) | (8u << 24))
#endif  // __CUDA_ARCH_FEAT_SM103_ALL

// Kahan + TwoProd accumulate (round 10, proven).
__device__ __forceinline__ void kacc(float x, float w, float& s, float& c) {
    float p = __fmul_rn(x, w);
    float e = __fmaf_rn(x, w, -p);
    float t = __fadd_rn(s, p);
    float z = __fsub_rn(t, s);
    float g = __fadd_rn(__fsub_rn(s, __fsub_rn(t, z)), __fsub_rn(p, z));
    c = __fadd_rn(c, __fadd_rn(g, e));
    s = t;
}
__device__ __forceinline__ void kmerge(float so, float co, float& s, float& c) {
    float t = __fadd_rn(s, so);
    float z = __fsub_rn(t, s);
    float g = __fadd_rn(__fsub_rn(s, __fsub_rn(t, z)), __fsub_rn(so, z));
    c = __fadd_rn(c, __fadd_rn(g, co));
    s = t;
}

// ---- setup -----------------------------------------------------------------
__global__ void init_kernel() {
    if (threadIdx.x < 6) g_cnt[threadIdx.x] = 0;
}

__global__ void route_conv_kernel(const float* __restrict__ img,
                                  const float* __restrict__ txt,
                                  const float* __restrict__ Wrq,
                                  const float* __restrict__ Wrk) {
    int warp = (blockIdx.x * blockDim.x + threadIdx.x) >> 5;
    int lane = threadIdx.x & 31;
    int side = blockIdx.y;
    if (warp >= MROWS) return;

    const float* x;  const float* wr;  __half* y;  int dim;
    if (side == 0) { x = img + (size_t)warp * IMG_DIM; wr = Wrq;
                     y = c_img + (size_t)warp * IMG_DIM; dim = IMG_DIM; }
    else           { x = txt + (size_t)warp * TXT_DIM; wr = Wrk;
                     y = c_txt + (size_t)warp * TXT_DIM; dim = TXT_DIM; }

    float s0 = 0.f, s1 = 0.f, s2 = 0.f, e0 = 0.f, e1 = 0.f, e2 = 0.f;
    for (int k0 = 0; k0 < dim; k0 += 128) {
        int k = k0 + lane * 4;
        float4 xv = *reinterpret_cast<const float4*>(x + k);

        __half2 h0 = __floats2half2_rn(xv.x, xv.y);
        __half2 h1 = __floats2half2_rn(xv.z, xv.w);
        uint2 o;
        o.x = *reinterpret_cast<uint32_t*>(&h0);
        o.y = *reinterpret_cast<uint32_t*>(&h1);
        *reinterpret_cast<uint2*>(y + k) = o;

        float4 w0 = *reinterpret_cast<const float4*>(wr + k);
        float4 w1 = *reinterpret_cast<const float4*>(wr + dim + k);
        float4 w2 = *reinterpret_cast<const float4*>(wr + 2 * dim + k);
        kacc(xv.x, w0.x, s0, e0); kacc(xv.y, w0.y, s0, e0);
        kacc(xv.z, w0.z, s0, e0); kacc(xv.w, w0.w, s0, e0);
        kacc(xv.x, w1.x, s1, e1); kacc(xv.y, w1.y, s1, e1);
        kacc(xv.z, w1.z, s1, e1); kacc(xv.w, w1.w, s1, e1);
        kacc(xv.x, w2.x, s2, e2); kacc(xv.y, w2.y, s2, e2);
        kacc(xv.z, w2.z, s2, e2); kacc(xv.w, w2.w, s2, e2);
    }
    #pragma unroll
    for (int off = 16; off; off >>= 1) {
        float a, b;
        a = __shfl_down_sync(0xffffffffu, s0, off);
        b = __shfl_down_sync(0xffffffffu, e0, off);
        kmerge(a, b, s0, e0);
        a = __shfl_down_sync(0xffffffffu, s1, off);
        b = __shfl_down_sync(0xffffffffu, e1, off);
        kmerge(a, b, s1, e1);
        a = __shfl_down_sync(0xffffffffu, s2, off);
        b = __shfl_down_sync(0xffffffffu, e2, off);
        kmerge(a, b, s2, e2);
    }

    double v0 = 0, v1 = 0, v2 = 0;
    int need64 = 0;
    if (lane == 0) {
        v0 = (double)s0 + (double)e0;
        v1 = (double)s1 + (double)e1;
        v2 = (double)s2 + (double)e2;
        double hi = v0 > v1 ? (v0 > v2 ? v0 : v2) : (v1 > v2 ? v1 : v2);
        double mid = v0 + v1 + v2
                   - hi
                   - (v0 < v1 ? (v0 < v2 ? v0 : v2) : (v1 < v2 ? v1 : v2));
        need64 = (hi - mid) < 1e-2;
    }
    need64 = __shfl_sync(0xffffffffu, need64, 0);

    if (need64) {
        double d0 = 0, d1 = 0, d2 = 0;
        for (int k = lane; k < dim; k += 32) {
            double xv = (double)x[k];
            d0 += xv * (double)wr[k];
            d1 += xv * (double)wr[dim + k];
            d2 += xv * (double)wr[2 * dim + k];
        }
        #pragma unroll
        for (int off = 16; off; off >>= 1) {
            d0 += __shfl_down_sync(0xffffffffu, d0, off);
            d1 += __shfl_down_sync(0xffffffffu, d1, off);
            d2 += __shfl_down_sync(0xffffffffu, d2, off);
        }
        if (lane == 0) { v0 = d0; v1 = d1; v2 = d2; }
    }

    if (lane == 0) {
        int p = 0; double best = v0;
        if (v1 > best) { best = v1; p = 1; }
        if (v2 > best) { best = v2; p = 2; }
        int pos = atomicAdd(&g_cnt[side * 3 + p], 1);
        g_list[side * 3 + p][pos] = warp;
    }
}

struct WConvArgs {
    const float* src[5];
    __half*      dst[5];
    int          end[5];
};
__global__ void wconvert_kernel(WConvArgs a) {
    const int total = a.end[4];
    const int stride = gridDim.x * blockDim.x;
    for (int i = blockIdx.x * blockDim.x + threadIdx.x; i < total; i += stride) {
        int s = 0;
        #pragma unroll
        for (int t = 0; t < 4; t++) s += (i >= a.end[t]);
        int j = i - (s ? a.end[s - 1] : 0);
        const float4* p = reinterpret_cast<const float4*>(a.src[s]) + 2 * (size_t)j;
        float4 x = p[0], y = p[1];
        __half2 h0 = __floats2half2_rn(x.x, x.y);
        __half2 h1 = __floats2half2_rn(x.z, x.w);
        __half2 h2 = __floats2half2_rn(y.x, y.y);
        __half2 h3 = __floats2half2_rn(y.z, y.w);
        uint4 o;
        o.x = *reinterpret_cast<uint32_t*>(&h0);
        o.y = *reinterpret_cast<uint32_t*>(&h1);
        o.z = *reinterpret_cast<uint32_t*>(&h2);
        o.w = *reinterpret_cast<uint32_t*>(&h3);
        reinterpret_cast<uint4*>(a.dst[s])[j] = o;
    }
}

// ---- fused GEMM ------------------------------------------------------------
// tcgen05 path: CTA tile 128(M) x 512(N), Kc=64, 2-stage double buffer.
//   A stage 16 KB + B stage 64 KB = 80 KB x 2 = 160 KB.
// fallback:   loops the proven 128x256 HMMA body over the two N-halves.
// grid = (324, 2); tile schedule decoded per-CTA from blockIdx + g_cnt.
#define KC        64
#define A_BYTES   (128 * 128)             /* 16 KB */
#define B_BYTES   (512 * 128)             /* 64 KB (tc path) */
#define STG_BYTES (A_BYTES + B_BYTES)     /* 80 KB */
#define STAGES    2
#define CTRL_OFF  (STAGES * STG_BYTES)    /* 160 KB */
#define SMEM_TOTAL (CTRL_OFF + 1024)
#define GRID_X    324
// fallback layout (within the same smem block)
#define FB_B_BYTES   (256 * 128)
#define FB_STG_BYTES (A_BYTES + FB_B_BYTES)   /* 48 KB */
#define FB_STAGES    3                        /* 144 KB < CTRL_OFF */

__global__ void __launch_bounds__(256, 1)
hmma_gemm(float* __restrict__ out)
{
    extern __shared__ char smem[];
    const int bx = blockIdx.x;

    const __half* A;  const __half* W;
    long long outBase;  int K, slot, rowBase;

    if (bx < 192) {
        int g = bx >> 6, t = bx & 63;
        rowBase = t * 128;  slot = -1;
        if (g == 0)      { A = c_img; W = c_wq; outBase = 0;          K = IMG_DIM; }
        else if (g == 1) { A = c_txt; W = c_wk; outBase = TELEMS;     K = TXT_DIM; }
        else             { A = c_txt; W = c_wv; outBase = 2 * TELEMS; K = TXT_DIM; }
    } else if (bx < 258) {
        int t = bx - 192;
        int c0 = (g_cnt[0] + 127) >> 7, c1 = (g_cnt[1] + 127) >> 7,
            c2 = (g_cnt[2] + 127) >> 7;
        int p, loc;
        if (t < c0)            { p = 0; loc = t; }
        else if (t < c0 + c1)  { p = 1; loc = t - c0; }
        else if (t < c0 + c1 + c2) { p = 2; loc = t - c0 - c1; }
        else return;
        A = c_img;  W = c_wqb + (size_t)p * INNER * IMG_DIM;
        outBase = 3 * TELEMS;  K = IMG_DIM;  slot = p;  rowBase = loc * 128;
    } else {
        int t = bx - 258;
        int c0 = (g_cnt[3] + 127) >> 7, c1 = (g_cnt[4] + 127) >> 7,
            c2 = (g_cnt[5] + 127) >> 7;
        int p, loc;
        if (t < c0)            { p = 0; loc = t; }
        else if (t < c0 + c1)  { p = 1; loc = t - c0; }
        else if (t < c0 + c1 + c2) { p = 2; loc = t - c0 - c1; }
        else return;
        A = c_txt;  W = c_wkb + (size_t)p * INNER * TXT_DIM;
        outBase = 4 * TELEMS;  K = TXT_DIM;  slot = 3 + p;  rowBase = loc * 128;
    }

    const int NCHUNK = K / KC;
    const int cnt = (slot >= 0) ? g_cnt[slot] : MROWS;

    const int tid  = threadIdx.x;
    const int wid  = tid >> 5;
    const int lane = tid & 31;

    const uint32_t sb = smem_u32(smem);
    int* s_rowmap = (int*)(smem + CTRL_OFF);
    if (tid < 128) {
        int gr = rowBase + tid;
        s_rowmap[tid] = (slot < 0) ? gr : ((gr < cnt) ? g_list[slot][gr] : 0);
    }

#if defined(__CUDA_ARCH_FEAT_SM103_ALL)
    // ======================= tcgen05 path: 128x512 ==========================
    const int colBase = blockIdx.y * 512;

    auto load_stage = [&](int buf, int chunk) {
        const int kc = chunk * KC;
        const uint32_t base = sb + buf * STG_BYTES;
        #pragma unroll
        for (int j = 0; j < 4; j++) {                  // A: 1024 x 16B
            int t = tid + j * 256;
            int r = t >> 3, c = t & 7;
            const __half* g = A + (size_t)s_rowmap[r] * K + kc + c * 8;
            cp16(base + SWZ(r * 128 + c * 16), g);
        }
        #pragma unroll
        for (int j = 0; j < 16; j++) {                 // B: 4096 x 16B (512 rows)
            int t = tid + j * 256;
            int r = t >> 3, c = t & 7;
            const __half* g = W + (size_t)(colBase + r) * K + kc + c * 8;
            cp16(base + A_BYTES + SWZ(r * 128 + c * 16), g);
        }
    };

    const uint32_t mbar0 = sb + CTRL_OFF + 512;
    const uint32_t tptr  = sb + CTRL_OFF + 576;
    if (tid == 0)
        for (int s = 0; s < STAGES; s++) mbar_init(mbar0 + 8 * s, 1);
    if (wid == 0) tc_alloc(tptr, 512);
    __syncthreads();

    uint32_t tmem;
    asm volatile("ld.shared.b32 %0, [%1];" : "=r"(tmem) : "r"(tptr));

    load_stage(0, 0); cp_commit();
    if (NCHUNK > 1) { load_stage(1, 1); cp_commit(); }

    int ph[STAGES];
    #pragma unroll
    for (int s = 0; s < STAGES; s++) ph[s] = 0;

    for (int i = 0; i < NCHUNK; i++) {
        const int buf = i & 1;
        cp_wait<1>();
        fence_gen_to_async();
        __syncthreads();

        if (tid == 0) {
            uint64_t ad = make_desc(sb + buf * STG_BYTES);
            #pragma unroll
            for (int nh = 0; nh < 2; nh++) {
                uint64_t bd = make_desc(sb + buf * STG_BYTES + A_BYTES + nh * 32768);
                #pragma unroll
                for (int ks = 0; ks < 4; ks++)
                    mma_f16_ss(tmem + nh * 256, ad + ks * 2, bd + ks * 2, TC_IDESC,
                               (i > 0) || (ks > 0));
            }
            tc_commit(mbar0 + 8 * buf);
        }

        if (i + 2 < NCHUNK) {
            mbar_wait(mbar0 + 8 * buf, ph[buf]);   // MMA(i) done -> buf reusable
            ph[buf] ^= 1;
            load_stage(buf, i + 2);
        }
        cp_commit();
    }

    {
        int lb = (NCHUNK - 1) & 1;
        mbar_wait(mbar0 + 8 * lb, ph[lb]);
    }
    tc_fence_after();

    // epilogue: warp w -> rows (w&3)*32+lane, col block (w>>2)*256 (8 x 32)
    {
        const int sp  = wid & 3;
        const int grp = wid >> 2;
        const int row = sp * 32 + lane;
        const bool valid = (rowBase + row) < cnt;
        const int mt = s_rowmap[row];
        const int bb = mt >> 10, sq = mt & 1023;
        #pragma unroll
        for (int cc = 0; cc < 8; cc++) {
            const int c0 = grp * 256 + cc * 32;
            uint32_t r[32];
            TC_LD_X32(r, tmem + c0);
            tc_wait_ld();
            if (valid) {
                const int n0 = colBase + c0;
                const int h = n0 >> 6, d0 = n0 & 63;
                long long off = outBase + (((long long)(bb * 16 + h) * 1024 + sq) * 64) + d0;
                float4* p = reinterpret_cast<float4*>(out + off);
                #pragma unroll
                for (int q = 0; q < 8; q++)
                    p[q] = make_float4(__uint_as_float(r[4 * q + 0]),
                                       __uint_as_float(r[4 * q + 1]),
                                       __uint_as_float(r[4 * q + 2]),
                                       __uint_as_float(r[4 * q + 3]));
            }
        }
    }
    tc_fence_before();
    __syncthreads();
    if (wid == 0) {
        tc_relinquish();
        tc_dealloc(tmem, 512);
    }
#else
    // ============ HMMA fallback: two sequential 128x256 passes ==============
    __syncthreads();

    const int wm = (wid & 1) * 64;
    const int wn = (wid >> 1) * 64;

    for (int nh = 0; nh < 2; nh++) {
        const int colBase = blockIdx.y * 512 + nh * 256;

        auto load_stage_f = [&](int buf, int chunk) {
            const int kc = chunk * KC;
            const uint32_t base = sb + buf * FB_STG_BYTES;
            #pragma unroll
            for (int j = 0; j < 4; j++) {
                int t = tid + j * 256;
                int r = t >> 3, c = t & 7;
                const __half* g = A + (size_t)s_rowmap[r] * K + kc + c * 8;
                cp16(base + SWZ(r * 128 + c * 16), g);
            }
            #pragma unroll
            for (int j = 0; j < 8; j++) {
                int t = tid + j * 256;
                int r = t >> 3, c = t & 7;
                const __half* g = W + (size_t)(colBase + r) * K + kc + c * 8;
                cp16(base + A_BYTES + SWZ(r * 128 + c * 16), g);
            }
        };

        float acc[4][8][4];
        #pragma unroll
        for (int m = 0; m < 4; m++)
            #pragma unroll
            for (int n = 0; n < 8; n++)
                #pragma unroll
                for (int q = 0; q < 4; q++) acc[m][n][q] = 0.f;

        load_stage_f(0, 0); cp_commit();
        load_stage_f(1, 1); cp_commit();

        for (int c = 0; c < NCHUNK; c++) {
            const int buf = c % FB_STAGES;
            cp_wait<FB_STAGES - 2>();
            __syncthreads();

            if (c + 2 < NCHUNK) load_stage_f((c + 2) % FB_STAGES, c + 2);
            cp_commit();

            const uint32_t aB = sb + buf * FB_STG_BYTES;
            const uint32_t bB = aB + A_BYTES;

            #pragma unroll
            for (int ks = 0; ks < 4; ks++) {
                uint32_t a[4][4];
                #pragma unroll
                for (int m = 0; m < 4; m++) {
                    int row = wm + m * 16 + (lane & 15);
                    int c16 = ks * 2 + (lane >> 4);
                    ldsm_x4(a[m][0], a[m][1], a[m][2], a[m][3],
                            aB + SWZ(row * 128 + c16 * 16));
                }
                uint32_t b[8][2];
                #pragma unroll
                for (int t = 0; t < 4; t++) {
                    int nrow = wn + t * 16 + (lane & 7) + ((lane >> 4) << 3);
                    int c16  = ks * 2 + ((lane >> 3) & 1);
                    uint32_t r0, r1, r2, r3;
                    ldsm_x4(r0, r1, r2, r3, bB + SWZ(nrow * 128 + c16 * 16));
                    b[2 * t][0] = r0;     b[2 * t][1] = r1;
                    b[2 * t + 1][0] = r2; b[2 * t + 1][1] = r3;
                }
                #pragma unroll
                for (int m = 0; m < 4; m++)
                    #pragma unroll
                    for (int n = 0; n < 8; n++)
                        mma16816(acc[m][n], a[m], b[n]);
            }
            __syncthreads();
        }

        const int head = (colBase + wn) >> 6;
        #pragma unroll
        for (int m = 0; m < 4; m++) {
            #pragma unroll
            for (int half = 0; half < 2; half++) {
                int rr = wm + m * 16 + (lane >> 2) + half * 8;
                if (rowBase + rr >= cnt) continue;
                int mt = s_rowmap[rr];
                int bb = mt >> 10, sq = mt & 1023;
                long long off0 = outBase + (((long long)(bb * 16 + head) * 1024 + sq) * 64);
                #pragma unroll
                for (int n = 0; n < 8; n++) {
                    int dd = n * 8 + 2 * (lane & 3);
                    float2 v = make_float2(acc[m][n][half * 2], acc[m][n][half * 2 + 1]);
                    *reinterpret_cast<float2*>(out + off0 + dd) = v;
                }
            }
        }
        __syncthreads();
    }
#endif
}

// ---- host ------------------------------------------------------------------
extern "C" void kernel_launch(void* const* d_in, const int* in_sizes, int n_in,
                              void* d_out, int out_size) {
    (void)in_sizes; (void)n_in; (void)out_size;
    const float* img = (const float*)d_in[0];
    const float* txt = (const float*)d_in[1];
    const float* Wq  = (const float*)d_in[2];
    const float* Wk  = (const float*)d_in[3];
    const float* Wv  = (const float*)d_in[4];
    const float* Wqb = (const float*)d_in[5];
    const float* Wkb = (const float*)d_in[6];
    const float* Wrq = (const float*)d_in[7];
    const float* Wrk = (const float*)d_in[8];
    float* out = (float*)d_out;

    cudaFuncSetAttribute(hmma_gemm, cudaFuncAttributeMaxDynamicSharedMemorySize,
                         SMEM_TOTAL);

    init_kernel<<<1, 32>>>();
    route_conv_kernel<<<dim3(1024, 2), 256>>>(img, txt, Wrq, Wrk);

    __half *p_wq, *p_wk, *p_wv, *p_wqb, *p_wkb;
    cudaGetSymbolAddress((void**)&p_wq,  c_wq);
    cudaGetSymbolAddress((void**)&p_wk,  c_wk);
    cudaGetSymbolAddress((void**)&p_wv,  c_wv);
    cudaGetSymbolAddress((void**)&p_wqb, c_wqb);
    cudaGetSymbolAddress((void**)&p_wkb, c_wkb);

    WConvArgs wa;
    const float* srcs[5] = { Wq, Wk, Wv, Wqb, Wkb };
    __half* dsts[5] = { p_wq, p_wk, p_wv, p_wqb, p_wkb };
    int lens[5] = { INNER * IMG_DIM / 8, INNER * TXT_DIM / 8, INNER * TXT_DIM / 8,
                    3 * INNER * IMG_DIM / 8, 3 * INNER * TXT_DIM / 8 };
    int accum = 0;
    for (int i = 0; i < 5; i++) {
        wa.src[i] = srcs[i];
        wa.dst[i] = dsts[i];
        accum += lens[i];
        wa.end[i] = accum;
    }
    wconvert_kernel<<<1184, 256>>>(wa);

    hmma_gemm<<<dim3(GRID_X, 2), 256, SMEM_TOTAL>>>(out);
}

// round 14
// speedup vs baseline: 2.5518x; 1.0586x over previous
#include <cuda_runtime.h>
#include <cuda_fp16.h>
#include <cstdint>

// ---------------------------------------------------------------------------
// DynamicProjectionModule, tcgen05 GEMM (sm_103a-featured pass) with HMMA
// fallback for the plain compute_103 pass.
//
// Round 14: GEMM is at the chip's ABSOLUTE L2 bandwidth cap (~6.2 TB/s
// measured in both R11 and R13 despite different tiles/pipelines). Only byte
// reduction helps. CTA tile M=256 x N=256: two M=128 D-halves in TMEM
// (cols 0-255 / 256-511) share each B smem chunk, halving B-side L2 traffic
// (551 -> 276 MB; total 861 -> 729 MB). Stage = A0 16K + A1 16K + B 32K,
// 3-stage ring, proven R11 mbar pipeline.
// Router: Kahan fp32 + rare fp64 fallback (proven).
// ---------------------------------------------------------------------------

#define BSZ      8
#define SEQ      1024
#define IMG_DIM  1024
#define TXT_DIM  768
#define INNER    1024
#define MROWS    (BSZ * SEQ)
#define TELEMS   ((long long)MROWS * INNER)

// ---- device scratch --------------------------------------------------------
__device__ int g_cnt[6];
__device__ int g_list[6][MROWS];

__device__ __half c_img[MROWS * IMG_DIM];
__device__ __half c_txt[MROWS * TXT_DIM];
__device__ __half c_wq [INNER * IMG_DIM];
__device__ __half c_wk [INNER * TXT_DIM];
__device__ __half c_wv [INNER * TXT_DIM];
__device__ __half c_wqb[3 * INNER * IMG_DIM];
__device__ __half c_wkb[3 * INNER * TXT_DIM];

// ---- helpers ---------------------------------------------------------------
__device__ __forceinline__ uint32_t smem_u32(const void* p) {
    uint32_t a;
    asm("{ .reg .u64 t; cvta.to.shared.u64 t, %1; cvt.u32.u64 %0, t; }" : "=r"(a) : "l"(p));
    return a;
}
__device__ __forceinline__ void cp16(uint32_t d, const void* g) {
    asm volatile("cp.async.cg.shared.global [%0], [%1], 16;" :: "r"(d), "l"(g));
}
__device__ __forceinline__ void cp_commit() { asm volatile("cp.async.commit_group;" ::: "memory"); }
template<int N> __device__ __forceinline__ void cp_wait() {
    asm volatile("cp.async.wait_group %0;" :: "n"(N) : "memory");
}
__device__ __forceinline__ void ldsm_x4(uint32_t& r0, uint32_t& r1, uint32_t& r2, uint32_t& r3,
                                        uint32_t addr) {
    asm volatile("ldmatrix.sync.aligned.m8n8.x4.shared.b16 {%0,%1,%2,%3}, [%4];"
                 : "=r"(r0), "=r"(r1), "=r"(r2), "=r"(r3) : "r"(addr));
}
__device__ __forceinline__ void mma16816(float* c, const uint32_t* a, const uint32_t* b) {
    asm volatile("mma.sync.aligned.m16n8k16.row.col.f32.f16.f16.f32 "
                 "{%0,%1,%2,%3}, {%4,%5,%6,%7}, {%8,%9}, {%0,%1,%2,%3};"
                 : "+f"(c[0]), "+f"(c[1]), "+f"(c[2]), "+f"(c[3])
                 : "r"(a[0]), "r"(a[1]), "r"(a[2]), "r"(a[3]), "r"(b[0]), "r"(b[1]));
}
#define SWZ(x) ((x) ^ (((x) >> 3) & 0x70))

#if defined(__CUDA_ARCH_FEAT_SM103_ALL)
// ---- tcgen05 helpers (featured pass only) ----------------------------------
__device__ __forceinline__ void fence_gen_to_async() {
    asm volatile("fence.proxy.async.shared::cta;" ::: "memory");
}
__device__ __forceinline__ void mbar_init(uint32_t a, uint32_t c) {
    asm volatile("mbarrier.init.shared.b64 [%0], %1;" :: "r"(a), "r"(c) : "memory");
}
__device__ __forceinline__ void mbar_wait(uint32_t a, uint32_t parity) {
    asm volatile(
        "{\n\t.reg .pred P;\n\t"
        "W_%=:\n\t"
        "mbarrier.try_wait.parity.acquire.cta.shared::cta.b64 P, [%0], %1, 0x989680;\n\t"
        "@!P bra W_%=;\n\t}"
        :: "r"(a), "r"(parity) : "memory");
}
__device__ __forceinline__ void tc_commit(uint32_t mbar) {
    asm volatile(
        "tcgen05.commit.cta_group::1.mbarrier::arrive::one.shared::cluster.b64 [%0];"
        :: "r"(mbar) : "memory");
}
__device__ __forceinline__ void tc_alloc(uint32_t smem_dst, uint32_t ncols) {
    asm volatile("tcgen05.alloc.cta_group::1.sync.aligned.shared::cta.b32 [%0], %1;"
                 :: "r"(smem_dst), "r"(ncols) : "memory");
}
__device__ __forceinline__ void tc_dealloc(uint32_t tmem, uint32_t ncols) {
    asm volatile("tcgen05.dealloc.cta_group::1.sync.aligned.b32 %0, %1;" :: "r"(tmem), "r"(ncols));
}
__device__ __forceinline__ void tc_relinquish() {
    asm volatile("tcgen05.relinquish_alloc_permit.cta_group::1.sync.aligned;");
}
__device__ __forceinline__ void tc_fence_after() {
    asm volatile("tcgen05.fence::after_thread_sync;" ::: "memory");
}
__device__ __forceinline__ void tc_fence_before() {
    asm volatile("tcgen05.fence::before_thread_sync;" ::: "memory");
}
__device__ __forceinline__ void tc_wait_ld() {
    asm volatile("tcgen05.wait::ld.sync.aligned;" ::: "memory");
}
__device__ __forceinline__ void mma_f16_ss(uint32_t d_tmem, uint64_t a_desc, uint64_t b_desc,
                                           uint32_t idesc, bool accum) {
    uint32_t en = accum ? 1u : 0u;
    asm volatile(
        "{\n\t.reg .pred p;\n\t"
        "setp.ne.u32 p, %4, 0;\n\t"
        "tcgen05.mma.cta_group::1.kind::f16 [%0], %1, %2, %3, {%5, %5, %5, %5}, p;\n\t}"
        :: "r"(d_tmem), "l"(a_desc), "l"(b_desc), "r"(idesc), "r"(en), "r"(0u)
        : "memory");
}
#define TC_LD_X32(r, addr)                                                     \
    asm volatile("tcgen05.ld.sync.aligned.32x32b.x32.b32 "                     \
        "{%0,%1,%2,%3,%4,%5,%6,%7,%8,%9,%10,%11,%12,%13,%14,%15,"              \
        "%16,%17,%18,%19,%20,%21,%22,%23,%24,%25,%26,%27,%28,%29,%30,%31}, [%32];" \
        : "=r"((r)[0]),"=r"((r)[1]),"=r"((r)[2]),"=r"((r)[3]),                 \
          "=r"((r)[4]),"=r"((r)[5]),"=r"((r)[6]),"=r"((r)[7]),                 \
          "=r"((r)[8]),"=r"((r)[9]),"=r"((r)[10]),"=r"((r)[11]),               \
          "=r"((r)[12]),"=r"((r)[13]),"=r"((r)[14]),"=r"((r)[15]),             \
          "=r"((r)[16]),"=r"((r)[17]),"=r"((r)[18]),"=r"((r)[19]),             \
          "=r"((r)[20]),"=r"((r)[21]),"=r"((r)[22]),"=r"((r)[23]),             \
          "=r"((r)[24]),"=r"((r)[25]),"=r"((r)[26]),"=r"((r)[27]),             \
          "=r"((r)[28]),"=r"((r)[29]),"=r"((r)[30]),"=r"((r)[31])              \
        : "r"(addr))
static __device__ __forceinline__ uint64_t make_desc(uint32_t addr) {
    return (uint64_t(2) << 61) | (uint64_t(1) << 46) | (uint64_t(64) << 32)
         | (uint64_t(1) << 16) | ((uint64_t)(addr >> 4) & 0x3FFF);
}
// idesc: dtype F32, atype=btype=F16, N=256, M=128
#define TC_IDESC ((1u << 4) | (32u << 17) | (8u << 24))
#endif  // __CUDA_ARCH_FEAT_SM103_ALL

// Kahan + TwoProd accumulate (proven).
__device__ __forceinline__ void kacc(float x, float w, float& s, float& c) {
    float p = __fmul_rn(x, w);
    float e = __fmaf_rn(x, w, -p);
    float t = __fadd_rn(s, p);
    float z = __fsub_rn(t, s);
    float g = __fadd_rn(__fsub_rn(s, __fsub_rn(t, z)), __fsub_rn(p, z));
    c = __fadd_rn(c, __fadd_rn(g, e));
    s = t;
}
__device__ __forceinline__ void kmerge(float so, float co, float& s, float& c) {
    float t = __fadd_rn(s, so);
    float z = __fsub_rn(t, s);
    float g = __fadd_rn(__fsub_rn(s, __fsub_rn(t, z)), __fsub_rn(so, z));
    c = __fadd_rn(c, __fadd_rn(g, co));
    s = t;
}

// ---- setup -----------------------------------------------------------------
__global__ void init_kernel() {
    if (threadIdx.x < 6) g_cnt[threadIdx.x] = 0;
}

__global__ void route_conv_kernel(const float* __restrict__ img,
                                  const float* __restrict__ txt,
                                  const float* __restrict__ Wrq,
                                  const float* __restrict__ Wrk) {
    int warp = (blockIdx.x * blockDim.x + threadIdx.x) >> 5;
    int lane = threadIdx.x & 31;
    int side = blockIdx.y;
    if (warp >= MROWS) return;

    const float* x;  const float* wr;  __half* y;  int dim;
    if (side == 0) { x = img + (size_t)warp * IMG_DIM; wr = Wrq;
                     y = c_img + (size_t)warp * IMG_DIM; dim = IMG_DIM; }
    else           { x = txt + (size_t)warp * TXT_DIM; wr = Wrk;
                     y = c_txt + (size_t)warp * TXT_DIM; dim = TXT_DIM; }

    float s0 = 0.f, s1 = 0.f, s2 = 0.f, e0 = 0.f, e1 = 0.f, e2 = 0.f;
    for (int k0 = 0; k0 < dim; k0 += 128) {
        int k = k0 + lane * 4;
        float4 xv = *reinterpret_cast<const float4*>(x + k);

        __half2 h0 = __floats2half2_rn(xv.x, xv.y);
        __half2 h1 = __floats2half2_rn(xv.z, xv.w);
        uint2 o;
        o.x = *reinterpret_cast<uint32_t*>(&h0);
        o.y = *reinterpret_cast<uint32_t*>(&h1);
        *reinterpret_cast<uint2*>(y + k) = o;

        float4 w0 = *reinterpret_cast<const float4*>(wr + k);
        float4 w1 = *reinterpret_cast<const float4*>(wr + dim + k);
        float4 w2 = *reinterpret_cast<const float4*>(wr + 2 * dim + k);
        kacc(xv.x, w0.x, s0, e0); kacc(xv.y, w0.y, s0, e0);
        kacc(xv.z, w0.z, s0, e0); kacc(xv.w, w0.w, s0, e0);
        kacc(xv.x, w1.x, s1, e1); kacc(xv.y, w1.y, s1, e1);
        kacc(xv.z, w1.z, s1, e1); kacc(xv.w, w1.w, s1, e1);
        kacc(xv.x, w2.x, s2, e2); kacc(xv.y, w2.y, s2, e2);
        kacc(xv.z, w2.z, s2, e2); kacc(xv.w, w2.w, s2, e2);
    }
    #pragma unroll
    for (int off = 16; off; off >>= 1) {
        float a, b;
        a = __shfl_down_sync(0xffffffffu, s0, off);
        b = __shfl_down_sync(0xffffffffu, e0, off);
        kmerge(a, b, s0, e0);
        a = __shfl_down_sync(0xffffffffu, s1, off);
        b = __shfl_down_sync(0xffffffffu, e1, off);
        kmerge(a, b, s1, e1);
        a = __shfl_down_sync(0xffffffffu, s2, off);
        b = __shfl_down_sync(0xffffffffu, e2, off);
        kmerge(a, b, s2, e2);
    }

    double v0 = 0, v1 = 0, v2 = 0;
    int need64 = 0;
    if (lane == 0) {
        v0 = (double)s0 + (double)e0;
        v1 = (double)s1 + (double)e1;
        v2 = (double)s2 + (double)e2;
        double hi = v0 > v1 ? (v0 > v2 ? v0 : v2) : (v1 > v2 ? v1 : v2);
        double mid = v0 + v1 + v2
                   - hi
                   - (v0 < v1 ? (v0 < v2 ? v0 : v2) : (v1 < v2 ? v1 : v2));
        need64 = (hi - mid) < 1e-2;
    }
    need64 = __shfl_sync(0xffffffffu, need64, 0);

    if (need64) {
        double d0 = 0, d1 = 0, d2 = 0;
        for (int k = lane; k < dim; k += 32) {
            double xv = (double)x[k];
            d0 += xv * (double)wr[k];
            d1 += xv * (double)wr[dim + k];
            d2 += xv * (double)wr[2 * dim + k];
        }
        #pragma unroll
        for (int off = 16; off; off >>= 1) {
            d0 += __shfl_down_sync(0xffffffffu, d0, off);
            d1 += __shfl_down_sync(0xffffffffu, d1, off);
            d2 += __shfl_down_sync(0xffffffffu, d2, off);
        }
        if (lane == 0) { v0 = d0; v1 = d1; v2 = d2; }
    }

    if (lane == 0) {
        int p = 0; double best = v0;
        if (v1 > best) { best = v1; p = 1; }
        if (v2 > best) { best = v2; p = 2; }
        int pos = atomicAdd(&g_cnt[side * 3 + p], 1);
        g_list[side * 3 + p][pos] = warp;
    }
}

struct WConvArgs {
    const float* src[5];
    __half*      dst[5];
    int          end[5];
};
__global__ void wconvert_kernel(WConvArgs a) {
    const int total = a.end[4];
    const int stride = gridDim.x * blockDim.x;
    for (int i = blockIdx.x * blockDim.x + threadIdx.x; i < total; i += stride) {
        int s = 0;
        #pragma unroll
        for (int t = 0; t < 4; t++) s += (i >= a.end[t]);
        int j = i - (s ? a.end[s - 1] : 0);
        const float4* p = reinterpret_cast<const float4*>(a.src[s]) + 2 * (size_t)j;
        float4 x = p[0], y = p[1];
        __half2 h0 = __floats2half2_rn(x.x, x.y);
        __half2 h1 = __floats2half2_rn(x.z, x.w);
        __half2 h2 = __floats2half2_rn(y.x, y.y);
        __half2 h3 = __floats2half2_rn(y.z, y.w);
        uint4 o;
        o.x = *reinterpret_cast<uint32_t*>(&h0);
        o.y = *reinterpret_cast<uint32_t*>(&h1);
        o.z = *reinterpret_cast<uint32_t*>(&h2);
        o.w = *reinterpret_cast<uint32_t*>(&h3);
        reinterpret_cast<uint4*>(a.dst[s])[j] = o;
    }
}

// ---- fused GEMM ------------------------------------------------------------
// tcgen05: CTA tile 256(M) x 256(N). Stage = A0 16K | A1 16K | B 32K = 64K,
// 3 stages (192 KB). D0 = TMEM cols 0-255 (rows 0-127), D1 = cols 256-511.
// Two M=128 MMA dispatches per k-step share the B chunk (B L2-read once).
// fallback: two sequential M=128 passes of the proven 128x256 HMMA body.
// grid = (166, 4): bx<96 static (32 tiles each of Q/K/V), [96,131) routed
// img, [131,166) routed txt; rowBase in units of 256.
#define KC        64
#define A_HALF    (128 * 128)             /* 16 KB */
#define A_BYTES   (2 * A_HALF)            /* 32 KB */
#define B_BYTES   (256 * 128)             /* 32 KB */
#define STG_BYTES (A_BYTES + B_BYTES)     /* 64 KB */
#define STAGES    3
#define CTRL_OFF  (STAGES * STG_BYTES)    /* 192 KB */
#define SMEM_TOTAL (CTRL_OFF + 2048)
#define GRID_X    166
// fallback layout
#define FB_STG_BYTES (A_HALF + B_BYTES)   /* 48 KB */
#define FB_STAGES    3                    /* 144 KB < CTRL_OFF */

__global__ void __launch_bounds__(256, 1)
hmma_gemm(float* __restrict__ out)
{
    extern __shared__ char smem[];
    const int bx = blockIdx.x;

    const __half* A;  const __half* W;
    long long outBase;  int K, slot, rowBase;

    if (bx < 96) {
        int g = bx >> 5, t = bx & 31;
        rowBase = t * 256;  slot = -1;
        if (g == 0)      { A = c_img; W = c_wq; outBase = 0;          K = IMG_DIM; }
        else if (g == 1) { A = c_txt; W = c_wk; outBase = TELEMS;     K = TXT_DIM; }
        else             { A = c_txt; W = c_wv; outBase = 2 * TELEMS; K = TXT_DIM; }
    } else if (bx < 131) {
        int t = bx - 96;
        int c0 = (g_cnt[0] + 255) >> 8, c1 = (g_cnt[1] + 255) >> 8,
            c2 = (g_cnt[2] + 255) >> 8;
        int p, loc;
        if (t < c0)            { p = 0; loc = t; }
        else if (t < c0 + c1)  { p = 1; loc = t - c0; }
        else if (t < c0 + c1 + c2) { p = 2; loc = t - c0 - c1; }
        else return;
        A = c_img;  W = c_wqb + (size_t)p * INNER * IMG_DIM;
        outBase = 3 * TELEMS;  K = IMG_DIM;  slot = p;  rowBase = loc * 256;
    } else {
        int t = bx - 131;
        int c0 = (g_cnt[3] + 255) >> 8, c1 = (g_cnt[4] + 255) >> 8,
            c2 = (g_cnt[5] + 255) >> 8;
        int p, loc;
        if (t < c0)            { p = 0; loc = t; }
        else if (t < c0 + c1)  { p = 1; loc = t - c0; }
        else if (t < c0 + c1 + c2) { p = 2; loc = t - c0 - c1; }
        else return;
        A = c_txt;  W = c_wkb + (size_t)p * INNER * TXT_DIM;
        outBase = 4 * TELEMS;  K = TXT_DIM;  slot = 3 + p;  rowBase = loc * 256;
    }

    const int NCHUNK = K / KC;
    const int colBase = blockIdx.y * 256;
    const int cnt = (slot >= 0) ? g_cnt[slot] : MROWS;

    const int tid  = threadIdx.x;
    const int wid  = tid >> 5;
    const int lane = tid & 31;

    const uint32_t sb = smem_u32(smem);
    int* s_rowmap = (int*)(smem + CTRL_OFF);
    if (tid < 256) {
        int gr = rowBase + tid;
        s_rowmap[tid] = (slot < 0) ? gr : ((gr < cnt) ? g_list[slot][gr] : 0);
    }

#if defined(__CUDA_ARCH_FEAT_SM103_ALL)
    // ======================= tcgen05 path: 256x256 ==========================
    auto load_stage = [&](int buf, int chunk) {
        const int kc = chunk * KC;
        const uint32_t base = sb + buf * STG_BYTES;
        #pragma unroll
        for (int j = 0; j < 8; j++) {                  // A: 2048 x 16B (256 rows)
            int t = tid + j * 256;
            int r = t >> 3, c = t & 7;
            const __half* g = A + (size_t)s_rowmap[r] * K + kc + c * 8;
            cp16(base + (r >> 7) * A_HALF + SWZ((r & 127) * 128 + c * 16), g);
        }
        #pragma unroll
        for (int j = 0; j < 8; j++) {                  // B: 2048 x 16B (256 rows)
            int t = tid + j * 256;
            int r = t >> 3, c = t & 7;
            const __half* g = W + (size_t)(colBase + r) * K + kc + c * 8;
            cp16(base + A_BYTES + SWZ(r * 128 + c * 16), g);
        }
    };

    const uint32_t mbar0 = sb + CTRL_OFF + 1536;
    const uint32_t tptr  = sb + CTRL_OFF + 1600;
    if (tid == 0)
        for (int s = 0; s < STAGES; s++) mbar_init(mbar0 + 8 * s, 1);
    if (wid == 0) tc_alloc(tptr, 512);
    __syncthreads();

    uint32_t tmem;
    asm volatile("ld.shared.b32 %0, [%1];" : "=r"(tmem) : "r"(tptr));

    load_stage(0, 0); cp_commit();
    load_stage(1, 1); cp_commit();

    int ph[STAGES];
    #pragma unroll
    for (int s = 0; s < STAGES; s++) ph[s] = 0;

    for (int i = 0; i < NCHUNK; i++) {
        const int buf = i % STAGES;
        cp_wait<STAGES - 2>();
        fence_gen_to_async();
        __syncthreads();

        if (tid == 0) {
            uint64_t ad0 = make_desc(sb + buf * STG_BYTES);
            uint64_t ad1 = make_desc(sb + buf * STG_BYTES + A_HALF);
            uint64_t bd  = make_desc(sb + buf * STG_BYTES + A_BYTES);
            #pragma unroll
            for (int ks = 0; ks < 4; ks++) {
                bool acc = (i > 0) || (ks > 0);
                mma_f16_ss(tmem,       ad0 + ks * 2, bd + ks * 2, TC_IDESC, acc);
                mma_f16_ss(tmem + 256, ad1 + ks * 2, bd + ks * 2, TC_IDESC, acc);
            }
            tc_commit(mbar0 + 8 * buf);
        }

        if (i + 2 < NCHUNK) {
            if (i >= 1) {
                int pb = (i - 1) % STAGES;
                mbar_wait(mbar0 + 8 * pb, ph[pb]);
                ph[pb] ^= 1;
            }
            load_stage((i + 2) % STAGES, i + 2);
        }
        cp_commit();
    }

    {
        int lb = (NCHUNK - 1) % STAGES;
        mbar_wait(mbar0 + 8 * lb, ph[lb]);
    }
    tc_fence_after();

    // epilogue: warp w: mh = w>>2 (D half), sp = w&3 (subpartition).
    // row_in_tile = mh*128 + sp*32 + lane; cols = mh*256 + cc*32 in TMEM,
    // output cols colBase + cc*32.
    {
        const int sp  = wid & 3;
        const int mh  = wid >> 2;
        const int row = mh * 128 + sp * 32 + lane;
        const bool valid = (rowBase + row) < cnt;
        const int mt = s_rowmap[row];
        const int bb = mt >> 10, sq = mt & 1023;
        #pragma unroll
        for (int cc = 0; cc < 8; cc++) {
            uint32_t r[32];
            TC_LD_X32(r, tmem + mh * 256 + cc * 32);
            tc_wait_ld();
            if (valid) {
                const int n0 = colBase + cc * 32;
                const int h = n0 >> 6, d0 = n0 & 63;
                long long off = outBase + (((long long)(bb * 16 + h) * 1024 + sq) * 64) + d0;
                float4* p = reinterpret_cast<float4*>(out + off);
                #pragma unroll
                for (int q = 0; q < 8; q++)
                    p[q] = make_float4(__uint_as_float(r[4 * q + 0]),
                                       __uint_as_float(r[4 * q + 1]),
                                       __uint_as_float(r[4 * q + 2]),
                                       __uint_as_float(r[4 * q + 3]));
            }
        }
    }
    tc_fence_before();
    __syncthreads();
    if (wid == 0) {
        tc_relinquish();
        tc_dealloc(tmem, 512);
    }
#else
    // ============ HMMA fallback: two sequential M=128 passes ================
    __syncthreads();

    const int wm = (wid & 1) * 64;
    const int wn = (wid >> 1) * 64;

    for (int mh = 0; mh < 2; mh++) {
        auto load_stage_f = [&](int buf, int chunk) {
            const int kc = chunk * KC;
            const uint32_t base = sb + buf * FB_STG_BYTES;
            #pragma unroll
            for (int j = 0; j < 4; j++) {
                int t = tid + j * 256;
                int r = t >> 3, c = t & 7;
                const __half* g = A + (size_t)s_rowmap[mh * 128 + r] * K + kc + c * 8;
                cp16(base + SWZ(r * 128 + c * 16), g);
            }
            #pragma unroll
            for (int j = 0; j < 8; j++) {
                int t = tid + j * 256;
                int r = t >> 3, c = t & 7;
                const __half* g = W + (size_t)(colBase + r) * K + kc + c * 8;
                cp16(base + A_HALF + SWZ(r * 128 + c * 16), g);
            }
        };

        float acc[4][8][4];
        #pragma unroll
        for (int m = 0; m < 4; m++)
            #pragma unroll
            for (int n = 0; n < 8; n++)
                #pragma unroll
                for (int q = 0; q < 4; q++) acc[m][n][q] = 0.f;

        load_stage_f(0, 0); cp_commit();
        load_stage_f(1, 1); cp_commit();

        for (int c = 0; c < NCHUNK; c++) {
            const int buf = c % FB_STAGES;
            cp_wait<FB_STAGES - 2>();
            __syncthreads();

            if (c + 2 < NCHUNK) load_stage_f((c + 2) % FB_STAGES, c + 2);
            cp_commit();

            const uint32_t aB = sb + buf * FB_STG_BYTES;
            const uint32_t bB = aB + A_HALF;

            #pragma unroll
            for (int ks = 0; ks < 4; ks++) {
                uint32_t a[4][4];
                #pragma unroll
                for (int m = 0; m < 4; m++) {
                    int row = wm + m * 16 + (lane & 15);
                    int c16 = ks * 2 + (lane >> 4);
                    ldsm_x4(a[m][0], a[m][1], a[m][2], a[m][3],
                            aB + SWZ(row * 128 + c16 * 16));
                }
                uint32_t b[8][2];
                #pragma unroll
                for (int t = 0; t < 4; t++) {
                    int nrow = wn + t * 16 + (lane & 7) + ((lane >> 4) << 3);
                    int c16  = ks * 2 + ((lane >> 3) & 1);
                    uint32_t r0, r1, r2, r3;
                    ldsm_x4(r0, r1, r2, r3, bB + SWZ(nrow * 128 + c16 * 16));
                    b[2 * t][0] = r0;     b[2 * t][1] = r1;
                    b[2 * t + 1][0] = r2; b[2 * t + 1][1] = r3;
                }
                #pragma unroll
                for (int m = 0; m < 4; m++)
                    #pragma unroll
                    for (int n = 0; n < 8; n++)
                        mma16816(acc[m][n], a[m], b[n]);
            }
            __syncthreads();
        }

        const int head = (colBase + wn) >> 6;
        #pragma unroll
        for (int m = 0; m < 4; m++) {
            #pragma unroll
            for (int half = 0; half < 2; half++) {
                int rr = mh * 128 + wm + m * 16 + (lane >> 2) + half * 8;
                if (rowBase + rr >= cnt) continue;
                int mt = s_rowmap[rr];
                int bb = mt >> 10, sq = mt & 1023;
                long long off0 = outBase + (((long long)(bb * 16 + head) * 1024 + sq) * 64);
                #pragma unroll
                for (int n = 0; n < 8; n++) {
                    int dd = n * 8 + 2 * (lane & 3);
                    float2 v = make_float2(acc[m][n][half * 2], acc[m][n][half * 2 + 1]);
                    *reinterpret_cast<float2*>(out + off0 + dd) = v;
                }
            }
        }
        __syncthreads();
    }
#endif
}

// ---- host ------------------------------------------------------------------
extern "C" void kernel_launch(void* const* d_in, const int* in_sizes, int n_in,
                              void* d_out, int out_size) {
    (void)in_sizes; (void)n_in; (void)out_size;
    const float* img = (const float*)d_in[0];
    const float* txt = (const float*)d_in[1];
    const float* Wq  = (const float*)d_in[2];
    const float* Wk  = (const float*)d_in[3];
    const float* Wv  = (const float*)d_in[4];
    const float* Wqb = (const float*)d_in[5];
    const float* Wkb = (const float*)d_in[6];
    const float* Wrq = (const float*)d_in[7];
    const float* Wrk = (const float*)d_in[8];
    float* out = (float*)d_out;

    cudaFuncSetAttribute(hmma_gemm, cudaFuncAttributeMaxDynamicSharedMemorySize,
                         SMEM_TOTAL);

    init_kernel<<<1, 32>>>();
    route_conv_kernel<<<dim3(1024, 2), 256>>>(img, txt, Wrq, Wrk);

    __half *p_wq, *p_wk, *p_wv, *p_wqb, *p_wkb;
    cudaGetSymbolAddress((void**)&p_wq,  c_wq);
    cudaGetSymbolAddress((void**)&p_wk,  c_wk);
    cudaGetSymbolAddress((void**)&p_wv,  c_wv);
    cudaGetSymbolAddress((void**)&p_wqb, c_wqb);
    cudaGetSymbolAddress((void**)&p_wkb, c_wkb);

    WConvArgs wa;
    const float* srcs[5] = { Wq, Wk, Wv, Wqb, Wkb };
    __half* dsts[5] = { p_wq, p_wk, p_wv, p_wqb, p_wkb };
    int lens[5] = { INNER * IMG_DIM / 8, INNER * TXT_DIM / 8, INNER * TXT_DIM / 8,
                    3 * INNER * IMG_DIM / 8, 3 * INNER * TXT_DIM / 8 };
    int accum = 0;
    for (int i = 0; i < 5; i++) {
        wa.src[i] = srcs[i];
        wa.dst[i] = dsts[i];
        accum += lens[i];
        wa.end[i] = accum;
    }
    wconvert_kernel<<<1184, 256>>>(wa);

    hmma_gemm<<<dim3(GRID_X, 4), 256, SMEM_TOTAL>>>(out);
}

// round 16
// speedup vs baseline: 2.6350x; 1.0326x over previous
#include <cuda_runtime.h>
#include <cuda_fp16.h>
#include <cstdint>

// ---------------------------------------------------------------------------
// DynamicProjectionModule, tcgen05 GEMM (sm_103a-featured pass) with HMMA
// fallback for the plain compute_103 pass.
//
// Round 15: overhead strip around the (proven, BW-bound) 256x256 GEMM.
//  (1) Router: plain fp32 FMA accumulation (error ~1e-5 << the unchanged
//      1e-2 fp64-fallback margin -> identical routing decisions), replacing
//      the 2x-costlier Kahan+TwoProd body.
//  (2) g_cnt init folded into wconvert (block 0), launched first: 4 -> 3
//      kernel launches.
// ---------------------------------------------------------------------------

#define BSZ      8
#define SEQ      1024
#define IMG_DIM  1024
#define TXT_DIM  768
#define INNER    1024
#define MROWS    (BSZ * SEQ)
#define TELEMS   ((long long)MROWS * INNER)

// ---- device scratch --------------------------------------------------------
__device__ int g_cnt[6];
__device__ int g_list[6][MROWS];

__device__ __half c_img[MROWS * IMG_DIM];
__device__ __half c_txt[MROWS * TXT_DIM];
__device__ __half c_wq [INNER * IMG_DIM];
__device__ __half c_wk [INNER * TXT_DIM];
__device__ __half c_wv [INNER * TXT_DIM];
__device__ __half c_wqb[3 * INNER * IMG_DIM];
__device__ __half c_wkb[3 * INNER * TXT_DIM];

// ---- helpers ---------------------------------------------------------------
__device__ __forceinline__ uint32_t smem_u32(const void* p) {
    uint32_t a;
    asm("{ .reg .u64 t; cvta.to.shared.u64 t, %1; cvt.u32.u64 %0, t; }" : "=r"(a) : "l"(p));
    return a;
}
__device__ __forceinline__ void cp16(uint32_t d, const void* g) {
    asm volatile("cp.async.cg.shared.global [%0], [%1], 16;" :: "r"(d), "l"(g));
}
__device__ __forceinline__ void cp_commit() { asm volatile("cp.async.commit_group;" ::: "memory"); }
template<int N> __device__ __forceinline__ void cp_wait() {
    asm volatile("cp.async.wait_group %0;" :: "n"(N) : "memory");
}
__device__ __forceinline__ void ldsm_x4(uint32_t& r0, uint32_t& r1, uint32_t& r2, uint32_t& r3,
                                        uint32_t addr) {
    asm volatile("ldmatrix.sync.aligned.m8n8.x4.shared.b16 {%0,%1,%2,%3}, [%4];"
                 : "=r"(r0), "=r"(r1), "=r"(r2), "=r"(r3) : "r"(addr));
}
__device__ __forceinline__ void mma16816(float* c, const uint32_t* a, const uint32_t* b) {
    asm volatile("mma.sync.aligned.m16n8k16.row.col.f32.f16.f16.f32 "
                 "{%0,%1,%2,%3}, {%4,%5,%6,%7}, {%8,%9}, {%0,%1,%2,%3};"
                 : "+f"(c[0]), "+f"(c[1]), "+f"(c[2]), "+f"(c[3])
                 : "r"(a[0]), "r"(a[1]), "r"(a[2]), "r"(a[3]), "r"(b[0]), "r"(b[1]));
}
#define SWZ(x) ((x) ^ (((x) >> 3) & 0x70))

#if defined(__CUDA_ARCH_FEAT_SM103_ALL)
// ---- tcgen05 helpers (featured pass only) ----------------------------------
__device__ __forceinline__ void fence_gen_to_async() {
    asm volatile("fence.proxy.async.shared::cta;" ::: "memory");
}
__device__ __forceinline__ void mbar_init(uint32_t a, uint32_t c) {
    asm volatile("mbarrier.init.shared.b64 [%0], %1;" :: "r"(a), "r"(c) : "memory");
}
__device__ __forceinline__ void mbar_wait(uint32_t a, uint32_t parity) {
    asm volatile(
        "{\n\t.reg .pred P;\n\t"
        "W_%=:\n\t"
        "mbarrier.try_wait.parity.acquire.cta.shared::cta.b64 P, [%0], %1, 0x989680;\n\t"
        "@!P bra W_%=;\n\t}"
        :: "r"(a), "r"(parity) : "memory");
}
__device__ __forceinline__ void tc_commit(uint32_t mbar) {
    asm volatile(
        "tcgen05.commit.cta_group::1.mbarrier::arrive::one.shared::cluster.b64 [%0];"
        :: "r"(mbar) : "memory");
}
__device__ __forceinline__ void tc_alloc(uint32_t smem_dst, uint32_t ncols) {
    asm volatile("tcgen05.alloc.cta_group::1.sync.aligned.shared::cta.b32 [%0], %1;"
                 :: "r"(smem_dst), "r"(ncols) : "memory");
}
__device__ __forceinline__ void tc_dealloc(uint32_t tmem, uint32_t ncols) {
    asm volatile("tcgen05.dealloc.cta_group::1.sync.aligned.b32 %0, %1;" :: "r"(tmem), "r"(ncols));
}
__device__ __forceinline__ void tc_relinquish() {
    asm volatile("tcgen05.relinquish_alloc_permit.cta_group::1.sync.aligned;");
}
__device__ __forceinline__ void tc_fence_after() {
    asm volatile("tcgen05.fence::after_thread_sync;" ::: "memory");
}
__device__ __forceinline__ void tc_fence_before() {
    asm volatile("tcgen05.fence::before_thread_sync;" ::: "memory");
}
__device__ __forceinline__ void tc_wait_ld() {
    asm volatile("tcgen05.wait::ld.sync.aligned;" ::: "memory");
}
__device__ __forceinline__ void mma_f16_ss(uint32_t d_tmem, uint64_t a_desc, uint64_t b_desc,
                                           uint32_t idesc, bool accum) {
    uint32_t en = accum ? 1u : 0u;
    asm volatile(
        "{\n\t.reg .pred p;\n\t"
        "setp.ne.u32 p, %4, 0;\n\t"
        "tcgen05.mma.cta_group::1.kind::f16 [%0], %1, %2, %3, {%5, %5, %5, %5}, p;\n\t}"
        :: "r"(d_tmem), "l"(a_desc), "l"(b_desc), "r"(idesc), "r"(en), "r"(0u)
        : "memory");
}
#define TC_LD_X32(r, addr)                                                     \
    asm volatile("tcgen05.ld.sync.aligned.32x32b.x32.b32 "                     \
        "{%0,%1,%2,%3,%4,%5,%6,%7,%8,%9,%10,%11,%12,%13,%14,%15,"              \
        "%16,%17,%18,%19,%20,%21,%22,%23,%24,%25,%26,%27,%28,%29,%30,%31}, [%32];" \
        : "=r"((r)[0]),"=r"((r)[1]),"=r"((r)[2]),"=r"((r)[3]),                 \
          "=r"((r)[4]),"=r"((r)[5]),"=r"((r)[6]),"=r"((r)[7]),                 \
          "=r"((r)[8]),"=r"((r)[9]),"=r"((r)[10]),"=r"((r)[11]),               \
          "=r"((r)[12]),"=r"((r)[13]),"=r"((r)[14]),"=r"((r)[15]),             \
          "=r"((r)[16]),"=r"((r)[17]),"=r"((r)[18]),"=r"((r)[19]),             \
          "=r"((r)[20]),"=r"((r)[21]),"=r"((r)[22]),"=r"((r)[23]),             \
          "=r"((r)[24]),"=r"((r)[25]),"=r"((r)[26]),"=r"((r)[27]),             \
          "=r"((r)[28]),"=r"((r)[29]),"=r"((r)[30]),"=r"((r)[31])              \
        : "r"(addr))
static __device__ __forceinline__ uint64_t make_desc(uint32_t addr) {
    return (uint64_t(2) << 61) | (uint64_t(1) << 46) | (uint64_t(64) << 32)
         | (uint64_t(1) << 16) | ((uint64_t)(addr >> 4) & 0x3FFF);
}
// idesc: dtype F32, atype=btype=F16, N=256, M=128
#define TC_IDESC ((1u << 4) | (32u << 17) | (8u << 24))
#endif  // __CUDA_ARCH_FEAT_SM103_ALL

// ---- setup -----------------------------------------------------------------

// Weight fp32 -> fp16 (8 elem/unit) + g_cnt init (block 0). Launched FIRST.
struct WConvArgs {
    const float* src[5];
    __half*      dst[5];
    int          end[5];
};
__global__ void wconvert_kernel(WConvArgs a) {
    if (blockIdx.x == 0 && threadIdx.x < 6) g_cnt[threadIdx.x] = 0;
    const int total = a.end[4];
    const int stride = gridDim.x * blockDim.x;
    for (int i = blockIdx.x * blockDim.x + threadIdx.x; i < total; i += stride) {
        int s = 0;
        #pragma unroll
        for (int t = 0; t < 4; t++) s += (i >= a.end[t]);
        int j = i - (s ? a.end[s - 1] : 0);
        const float4* p = reinterpret_cast<const float4*>(a.src[s]) + 2 * (size_t)j;
        float4 x = p[0], y = p[1];
        __half2 h0 = __floats2half2_rn(x.x, x.y);
        __half2 h1 = __floats2half2_rn(x.z, x.w);
        __half2 h2 = __floats2half2_rn(y.x, y.y);
        __half2 h3 = __floats2half2_rn(y.z, y.w);
        uint4 o;
        o.x = *reinterpret_cast<uint32_t*>(&h0);
        o.y = *reinterpret_cast<uint32_t*>(&h1);
        o.z = *reinterpret_cast<uint32_t*>(&h2);
        o.w = *reinterpret_cast<uint32_t*>(&h3);
        reinterpret_cast<uint4*>(a.dst[s])[j] = o;
    }
}

// Fused routing + fp32->fp16 activation convert. One warp per token.
// Plain fp32 FMA scores (abs err ~1e-5); fp64 warp recompute iff top-2
// margin < 1e-2 (unchanged, proven) -> routing decisions identical.
__global__ void route_conv_kernel(const float* __restrict__ img,
                                  const float* __restrict__ txt,
                                  const float* __restrict__ Wrq,
                                  const float* __restrict__ Wrk) {
    int warp = (blockIdx.x * blockDim.x + threadIdx.x) >> 5;
    int lane = threadIdx.x & 31;
    int side = blockIdx.y;
    if (warp >= MROWS) return;

    const float* x;  const float* wr;  __half* y;  int dim;
    if (side == 0) { x = img + (size_t)warp * IMG_DIM; wr = Wrq;
                     y = c_img + (size_t)warp * IMG_DIM; dim = IMG_DIM; }
    else           { x = txt + (size_t)warp * TXT_DIM; wr = Wrk;
                     y = c_txt + (size_t)warp * TXT_DIM; dim = TXT_DIM; }

    float s0 = 0.f, s1 = 0.f, s2 = 0.f;
    for (int k0 = 0; k0 < dim; k0 += 128) {
        int k = k0 + lane * 4;
        float4 xv = *reinterpret_cast<const float4*>(x + k);

        __half2 h0 = __floats2half2_rn(xv.x, xv.y);
        __half2 h1 = __floats2half2_rn(xv.z, xv.w);
        uint2 o;
        o.x = *reinterpret_cast<uint32_t*>(&h0);
        o.y = *reinterpret_cast<uint32_t*>(&h1);
        *reinterpret_cast<uint2*>(y + k) = o;

        float4 w0 = *reinterpret_cast<const float4*>(wr + k);
        float4 w1 = *reinterpret_cast<const float4*>(wr + dim + k);
        float4 w2 = *reinterpret_cast<const float4*>(wr + 2 * dim + k);
        s0 = __fmaf_rn(xv.x, w0.x, s0); s0 = __fmaf_rn(xv.y, w0.y, s0);
        s0 = __fmaf_rn(xv.z, w0.z, s0); s0 = __fmaf_rn(xv.w, w0.w, s0);
        s1 = __fmaf_rn(xv.x, w1.x, s1); s1 = __fmaf_rn(xv.y, w1.y, s1);
        s1 = __fmaf_rn(xv.z, w1.z, s1); s1 = __fmaf_rn(xv.w, w1.w, s1);
        s2 = __fmaf_rn(xv.x, w2.x, s2); s2 = __fmaf_rn(xv.y, w2.y, s2);
        s2 = __fmaf_rn(xv.z, w2.z, s2); s2 = __fmaf_rn(xv.w, w2.w, s2);
    }
    #pragma unroll
    for (int off = 16; off; off >>= 1) {
        s0 += __shfl_down_sync(0xffffffffu, s0, off);
        s1 += __shfl_down_sync(0xffffffffu, s1, off);
        s2 += __shfl_down_sync(0xffffffffu, s2, off);
    }

    double v0 = 0, v1 = 0, v2 = 0;
    int need64 = 0;
    if (lane == 0) {
        v0 = (double)s0; v1 = (double)s1; v2 = (double)s2;
        double hi = v0 > v1 ? (v0 > v2 ? v0 : v2) : (v1 > v2 ? v1 : v2);
        double mid = v0 + v1 + v2
                   - hi
                   - (v0 < v1 ? (v0 < v2 ? v0 : v2) : (v1 < v2 ? v1 : v2));
        need64 = (hi - mid) < 1e-2;
    }
    need64 = __shfl_sync(0xffffffffu, need64, 0);

    if (need64) {   // rare (~0.3% of tokens): exact fp64 recompute, warp-wide
        double d0 = 0, d1 = 0, d2 = 0;
        for (int k = lane; k < dim; k += 32) {
            double xv = (double)x[k];
            d0 += xv * (double)wr[k];
            d1 += xv * (double)wr[dim + k];
            d2 += xv * (double)wr[2 * dim + k];
        }
        #pragma unroll
        for (int off = 16; off; off >>= 1) {
            d0 += __shfl_down_sync(0xffffffffu, d0, off);
            d1 += __shfl_down_sync(0xffffffffu, d1, off);
            d2 += __shfl_down_sync(0xffffffffu, d2, off);
        }
        if (lane == 0) { v0 = d0; v1 = d1; v2 = d2; }
    }

    if (lane == 0) {
        int p = 0; double best = v0;
        if (v1 > best) { best = v1; p = 1; }
        if (v2 > best) { best = v2; p = 2; }
        int pos = atomicAdd(&g_cnt[side * 3 + p], 1);
        g_list[side * 3 + p][pos] = warp;
    }
}

// ---- fused GEMM (unchanged from round 14, proven) --------------------------
// tcgen05: CTA tile 256(M) x 256(N). Stage = A0 16K | A1 16K | B 32K = 64K,
// 3 stages (192 KB). D0 = TMEM cols 0-255 (rows 0-127), D1 = cols 256-511.
#define KC        64
#define A_HALF    (128 * 128)
#define A_BYTES   (2 * A_HALF)
#define B_BYTES   (256 * 128)
#define STG_BYTES (A_BYTES + B_BYTES)
#define STAGES    3
#define CTRL_OFF  (STAGES * STG_BYTES)    /* 192 KB */
#define SMEM_TOTAL (CTRL_OFF + 2048)
#define GRID_X    166
#define FB_STG_BYTES (A_HALF + B_BYTES)
#define FB_STAGES    3

__global__ void __launch_bounds__(256, 1)
hmma_gemm(float* __restrict__ out)
{
    extern __shared__ char smem[];
    const int bx = blockIdx.x;

    const __half* A;  const __half* W;
    long long outBase;  int K, slot, rowBase;

    if (bx < 96) {
        int g = bx >> 5, t = bx & 31;
        rowBase = t * 256;  slot = -1;
        if (g == 0)      { A = c_img; W = c_wq; outBase = 0;          K = IMG_DIM; }
        else if (g == 1) { A = c_txt; W = c_wk; outBase = TELEMS;     K = TXT_DIM; }
        else             { A = c_txt; W = c_wv; outBase = 2 * TELEMS; K = TXT_DIM; }
    } else if (bx < 131) {
        int t = bx - 96;
        int c0 = (g_cnt[0] + 255) >> 8, c1 = (g_cnt[1] + 255) >> 8,
            c2 = (g_cnt[2] + 255) >> 8;
        int p, loc;
        if (t < c0)            { p = 0; loc = t; }
        else if (t < c0 + c1)  { p = 1; loc = t - c0; }
        else if (t < c0 + c1 + c2) { p = 2; loc = t - c0 - c1; }
        else return;
        A = c_img;  W = c_wqb + (size_t)p * INNER * IMG_DIM;
        outBase = 3 * TELEMS;  K = IMG_DIM;  slot = p;  rowBase = loc * 256;
    } else {
        int t = bx - 131;
        int c0 = (g_cnt[3] + 255) >> 8, c1 = (g_cnt[4] + 255) >> 8,
            c2 = (g_cnt[5] + 255) >> 8;
        int p, loc;
        if (t < c0)            { p = 0; loc = t; }
        else if (t < c0 + c1)  { p = 1; loc = t - c0; }
        else if (t < c0 + c1 + c2) { p = 2; loc = t - c0 - c1; }
        else return;
        A = c_txt;  W = c_wkb + (size_t)p * INNER * TXT_DIM;
        outBase = 4 * TELEMS;  K = TXT_DIM;  slot = 3 + p;  rowBase = loc * 256;
    }

    const int NCHUNK = K / KC;
    const int colBase = blockIdx.y * 256;
    const int cnt = (slot >= 0) ? g_cnt[slot] : MROWS;

    const int tid  = threadIdx.x;
    const int wid  = tid >> 5;
    const int lane = tid & 31;

    const uint32_t sb = smem_u32(smem);
    int* s_rowmap = (int*)(smem + CTRL_OFF);
    if (tid < 256) {
        int gr = rowBase + tid;
        s_rowmap[tid] = (slot < 0) ? gr : ((gr < cnt) ? g_list[slot][gr] : 0);
    }

#if defined(__CUDA_ARCH_FEAT_SM103_ALL)
    // ======================= tcgen05 path: 256x256 ==========================
    auto load_stage = [&](int buf, int chunk) {
        const int kc = chunk * KC;
        const uint32_t base = sb + buf * STG_BYTES;
        #pragma unroll
        for (int j = 0; j < 8; j++) {
            int t = tid + j * 256;
            int r = t >> 3, c = t & 7;
            const __half* g = A + (size_t)s_rowmap[r] * K + kc + c * 8;
            cp16(base + (r >> 7) * A_HALF + SWZ((r & 127) * 128 + c * 16), g);
        }
        #pragma unroll
        for (int j = 0; j < 8; j++) {
            int t = tid + j * 256;
            int r = t >> 3, c = t & 7;
            const __half* g = W + (size_t)(colBase + r) * K + kc + c * 8;
            cp16(base + A_BYTES + SWZ(r * 128 + c * 16), g);
        }
    };

    const uint32_t mbar0 = sb + CTRL_OFF + 1536;
    const uint32_t tptr  = sb + CTRL_OFF + 1600;
    if (tid == 0)
        for (int s = 0; s < STAGES; s++) mbar_init(mbar0 + 8 * s, 1);
    if (wid == 0) tc_alloc(tptr, 512);
    __syncthreads();

    uint32_t tmem;
    asm volatile("ld.shared.b32 %0, [%1];" : "=r"(tmem) : "r"(tptr));

    load_stage(0, 0); cp_commit();
    load_stage(1, 1); cp_commit();

    int ph[STAGES];
    #pragma unroll
    for (int s = 0; s < STAGES; s++) ph[s] = 0;

    for (int i = 0; i < NCHUNK; i++) {
        const int buf = i % STAGES;
        cp_wait<STAGES - 2>();
        fence_gen_to_async();
        __syncthreads();

        if (tid == 0) {
            uint64_t ad0 = make_desc(sb + buf * STG_BYTES);
            uint64_t ad1 = make_desc(sb + buf * STG_BYTES + A_HALF);
            uint64_t bd  = make_desc(sb + buf * STG_BYTES + A_BYTES);
            #pragma unroll
            for (int ks = 0; ks < 4; ks++) {
                bool acc = (i > 0) || (ks > 0);
                mma_f16_ss(tmem,       ad0 + ks * 2, bd + ks * 2, TC_IDESC, acc);
                mma_f16_ss(tmem + 256, ad1 + ks * 2, bd + ks * 2, TC_IDESC, acc);
            }
            tc_commit(mbar0 + 8 * buf);
        }

        if (i + 2 < NCHUNK) {
            if (i >= 1) {
                int pb = (i - 1) % STAGES;
                mbar_wait(mbar0 + 8 * pb, ph[pb]);
                ph[pb] ^= 1;
            }
            load_stage((i + 2) % STAGES, i + 2);
        }
        cp_commit();
    }

    {
        int lb = (NCHUNK - 1) % STAGES;
        mbar_wait(mbar0 + 8 * lb, ph[lb]);
    }
    tc_fence_after();

    {
        const int sp  = wid & 3;
        const int mh  = wid >> 2;
        const int row = mh * 128 + sp * 32 + lane;
        const bool valid = (rowBase + row) < cnt;
        const int mt = s_rowmap[row];
        const int bb = mt >> 10, sq = mt & 1023;
        #pragma unroll
        for (int cc = 0; cc < 8; cc++) {
            uint32_t r[32];
            TC_LD_X32(r, tmem + mh * 256 + cc * 32);
            tc_wait_ld();
            if (valid) {
                const int n0 = colBase + cc * 32;
                const int h = n0 >> 6, d0 = n0 & 63;
                long long off = outBase + (((long long)(bb * 16 + h) * 1024 + sq) * 64) + d0;
                float4* p = reinterpret_cast<float4*>(out + off);
                #pragma unroll
                for (int q = 0; q < 8; q++)
                    p[q] = make_float4(__uint_as_float(r[4 * q + 0]),
                                       __uint_as_float(r[4 * q + 1]),
                                       __uint_as_float(r[4 * q + 2]),
                                       __uint_as_float(r[4 * q + 3]));
            }
        }
    }
    tc_fence_before();
    __syncthreads();
    if (wid == 0) {
        tc_relinquish();
        tc_dealloc(tmem, 512);
    }
#else
    // ============ HMMA fallback: two sequential M=128 passes ================
    __syncthreads();

    const int wm = (wid & 1) * 64;
    const int wn = (wid >> 1) * 64;

    for (int mh = 0; mh < 2; mh++) {
        auto load_stage_f = [&](int buf, int chunk) {
            const int kc = chunk * KC;
            const uint32_t base = sb + buf * FB_STG_BYTES;
            #pragma unroll
            for (int j = 0; j < 4; j++) {
                int t = tid + j * 256;
                int r = t >> 3, c = t & 7;
                const __half* g = A + (size_t)s_rowmap[mh * 128 + r] * K + kc + c * 8;
                cp16(base + SWZ(r * 128 + c * 16), g);
            }
            #pragma unroll
            for (int j = 0; j < 8; j++) {
                int t = tid + j * 256;
                int r = t >> 3, c = t & 7;
                const __half* g = W + (size_t)(colBase + r) * K + kc + c * 8;
                cp16(base + A_HALF + SWZ(r * 128 + c * 16), g);
            }
        };

        float acc[4][8][4];
        #pragma unroll
        for (int m = 0; m < 4; m++)
            #pragma unroll
            for (int n = 0; n < 8; n++)
                #pragma unroll
                for (int q = 0; q < 4; q++) acc[m][n][q] = 0.f;

        load_stage_f(0, 0); cp_commit();
        load_stage_f(1, 1); cp_commit();

        for (int c = 0; c < NCHUNK; c++) {
            const int buf = c % FB_STAGES;
            cp_wait<FB_STAGES - 2>();
            __syncthreads();

            if (c + 2 < NCHUNK) load_stage_f((c + 2) % FB_STAGES, c + 2);
            cp_commit();

            const uint32_t aB = sb + buf * FB_STG_BYTES;
            const uint32_t bB = aB + A_HALF;

            #pragma unroll
            for (int ks = 0; ks < 4; ks++) {
                uint32_t a[4][4];
                #pragma unroll
                for (int m = 0; m < 4; m++) {
                    int row = wm + m * 16 + (lane & 15);
                    int c16 = ks * 2 + (lane >> 4);
                    ldsm_x4(a[m][0], a[m][1], a[m][2], a[m][3],
                            aB + SWZ(row * 128 + c16 * 16));
                }
                uint32_t b[8][2];
                #pragma unroll
                for (int t = 0; t < 4; t++) {
                    int nrow = wn + t * 16 + (lane & 7) + ((lane >> 4) << 3);
                    int c16  = ks * 2 + ((lane >> 3) & 1);
                    uint32_t r0, r1, r2, r3;
                    ldsm_x4(r0, r1, r2, r3, bB + SWZ(nrow * 128 + c16 * 16));
                    b[2 * t][0] = r0;     b[2 * t][1] = r1;
                    b[2 * t + 1][0] = r2; b[2 * t + 1][1] = r3;
                }
                #pragma unroll
                for (int m = 0; m < 4; m++)
                    #pragma unroll
                    for (int n = 0; n < 8; n++)
                        mma16816(acc[m][n], a[m], b[n]);
            }
            __syncthreads();
        }

        const int head = (colBase + wn) >> 6;
        #pragma unroll
        for (int m = 0; m < 4; m++) {
            #pragma unroll
            for (int half = 0; half < 2; half++) {
                int rr = mh * 128 + wm + m * 16 + (lane >> 2) + half * 8;
                if (rowBase + rr >= cnt) continue;
                int mt = s_rowmap[rr];
                int bb = mt >> 10, sq = mt & 1023;
                long long off0 = outBase + (((long long)(bb * 16 + head) * 1024 + sq) * 64);
                #pragma unroll
                for (int n = 0; n < 8; n++) {
                    int dd = n * 8 + 2 * (lane & 3);
                    float2 v = make_float2(acc[m][n][half * 2], acc[m][n][half * 2 + 1]);
                    *reinterpret_cast<float2*>(out + off0 + dd) = v;
                }
            }
        }
        __syncthreads();
    }
#endif
}

// ---- host ------------------------------------------------------------------
extern "C" void kernel_launch(void* const* d_in, const int* in_sizes, int n_in,
                              void* d_out, int out_size) {
    (void)in_sizes; (void)n_in; (void)out_size;
    const float* img = (const float*)d_in[0];
    const float* txt = (const float*)d_in[1];
    const float* Wq  = (const float*)d_in[2];
    const float* Wk  = (const float*)d_in[3];
    const float* Wv  = (const float*)d_in[4];
    const float* Wqb = (const float*)d_in[5];
    const float* Wkb = (const float*)d_in[6];
    const float* Wrq = (const float*)d_in[7];
    const float* Wrk = (const float*)d_in[8];
    float* out = (float*)d_out;

    cudaFuncSetAttribute(hmma_gemm, cudaFuncAttributeMaxDynamicSharedMemorySize,
                         SMEM_TOTAL);

    __half *p_wq, *p_wk, *p_wv, *p_wqb, *p_wkb;
    cudaGetSymbolAddress((void**)&p_wq,  c_wq);
    cudaGetSymbolAddress((void**)&p_wk,  c_wk);
    cudaGetSymbolAddress((void**)&p_wv,  c_wv);
    cudaGetSymbolAddress((void**)&p_wqb, c_wqb);
    cudaGetSymbolAddress((void**)&p_wkb, c_wkb);

    WConvArgs wa;
    const float* srcs[5] = { Wq, Wk, Wv, Wqb, Wkb };
    __half* dsts[5] = { p_wq, p_wk, p_wv, p_wqb, p_wkb };
    int lens[5] = { INNER * IMG_DIM / 8, INNER * TXT_DIM / 8, INNER * TXT_DIM / 8,
                    3 * INNER * IMG_DIM / 8, 3 * INNER * TXT_DIM / 8 };
    int accum = 0;
    for (int i = 0; i < 5; i++) {
        wa.src[i] = srcs[i];
        wa.dst[i] = dsts[i];
        accum += lens[i];
        wa.end[i] = accum;
    }
    // wconvert also zeroes g_cnt (block 0) -> must run before route_conv.
    wconvert_kernel<<<1184, 256>>>(wa);
    route_conv_kernel<<<dim3(1024, 2), 256>>>(img, txt, Wrq, Wrk);
    hmma_gemm<<<dim3(GRID_X, 4), 256, SMEM_TOTAL>>>(out);
}

// round 17
// speedup vs baseline: 2.8042x; 1.0642x over previous
#include <cuda_runtime.h>
#include <cuda_fp16.h>
#include <cstdint>

// ---------------------------------------------------------------------------
// DynamicProjectionModule, tcgen05 GEMM (sm_103a-featured pass) with HMMA
// fallback for the plain compute_103 pass.
//
// Round 16: prep-pass overlap. Router(+activation convert) and weight
// convert are independent memory passes that were serializing in-stream
// (15.7 + ~25 us). Merged into ONE prep_kernel (blocks [0,2048) route,
// [2048,3232) wconvert) so they co-schedule; g_cnt init becomes a
// cudaMemsetAsync graph node ahead of it. GEMM (256x256 tcgen05, BW-bound
// at ~5.7 TB/s) unchanged.
// ---------------------------------------------------------------------------

#define BSZ      8
#define SEQ      1024
#define IMG_DIM  1024
#define TXT_DIM  768
#define INNER    1024
#define MROWS    (BSZ * SEQ)
#define TELEMS   ((long long)MROWS * INNER)

#define ROUTE_BLOCKS 2048            /* 8 warps/block x 2048 = 16384 tokens */
#define WCONV_BLOCKS 1184
#define PREP_BLOCKS  (ROUTE_BLOCKS + WCONV_BLOCKS)

// ---- device scratch --------------------------------------------------------
__device__ int g_cnt[6];
__device__ int g_list[6][MROWS];

__device__ __half c_img[MROWS * IMG_DIM];
__device__ __half c_txt[MROWS * TXT_DIM];
__device__ __half c_wq [INNER * IMG_DIM];
__device__ __half c_wk [INNER * TXT_DIM];
__device__ __half c_wv [INNER * TXT_DIM];
__device__ __half c_wqb[3 * INNER * IMG_DIM];
__device__ __half c_wkb[3 * INNER * TXT_DIM];

// ---- helpers ---------------------------------------------------------------
__device__ __forceinline__ uint32_t smem_u32(const void* p) {
    uint32_t a;
    asm("{ .reg .u64 t; cvta.to.shared.u64 t, %1; cvt.u32.u64 %0, t; }" : "=r"(a) : "l"(p));
    return a;
}
__device__ __forceinline__ void cp16(uint32_t d, const void* g) {
    asm volatile("cp.async.cg.shared.global [%0], [%1], 16;" :: "r"(d), "l"(g));
}
__device__ __forceinline__ void cp_commit() { asm volatile("cp.async.commit_group;" ::: "memory"); }
template<int N> __device__ __forceinline__ void cp_wait() {
    asm volatile("cp.async.wait_group %0;" :: "n"(N) : "memory");
}
__device__ __forceinline__ void ldsm_x4(uint32_t& r0, uint32_t& r1, uint32_t& r2, uint32_t& r3,
                                        uint32_t addr) {
    asm volatile("ldmatrix.sync.aligned.m8n8.x4.shared.b16 {%0,%1,%2,%3}, [%4];"
                 : "=r"(r0), "=r"(r1), "=r"(r2), "=r"(r3) : "r"(addr));
}
__device__ __forceinline__ void mma16816(float* c, const uint32_t* a, const uint32_t* b) {
    asm volatile("mma.sync.aligned.m16n8k16.row.col.f32.f16.f16.f32 "
                 "{%0,%1,%2,%3}, {%4,%5,%6,%7}, {%8,%9}, {%0,%1,%2,%3};"
                 : "+f"(c[0]), "+f"(c[1]), "+f"(c[2]), "+f"(c[3])
                 : "r"(a[0]), "r"(a[1]), "r"(a[2]), "r"(a[3]), "r"(b[0]), "r"(b[1]));
}
#define SWZ(x) ((x) ^ (((x) >> 3) & 0x70))

#if defined(__CUDA_ARCH_FEAT_SM103_ALL)
// ---- tcgen05 helpers (featured pass only) ----------------------------------
__device__ __forceinline__ void fence_gen_to_async() {
    asm volatile("fence.proxy.async.shared::cta;" ::: "memory");
}
__device__ __forceinline__ void mbar_init(uint32_t a, uint32_t c) {
    asm volatile("mbarrier.init.shared.b64 [%0], %1;" :: "r"(a), "r"(c) : "memory");
}
__device__ __forceinline__ void mbar_wait(uint32_t a, uint32_t parity) {
    asm volatile(
        "{\n\t.reg .pred P;\n\t"
        "W_%=:\n\t"
        "mbarrier.try_wait.parity.acquire.cta.shared::cta.b64 P, [%0], %1, 0x989680;\n\t"
        "@!P bra W_%=;\n\t}"
        :: "r"(a), "r"(parity) : "memory");
}
__device__ __forceinline__ void tc_commit(uint32_t mbar) {
    asm volatile(
        "tcgen05.commit.cta_group::1.mbarrier::arrive::one.shared::cluster.b64 [%0];"
        :: "r"(mbar) : "memory");
}
__device__ __forceinline__ void tc_alloc(uint32_t smem_dst, uint32_t ncols) {
    asm volatile("tcgen05.alloc.cta_group::1.sync.aligned.shared::cta.b32 [%0], %1;"
                 :: "r"(smem_dst), "r"(ncols) : "memory");
}
__device__ __forceinline__ void tc_dealloc(uint32_t tmem, uint32_t ncols) {
    asm volatile("tcgen05.dealloc.cta_group::1.sync.aligned.b32 %0, %1;" :: "r"(tmem), "r"(ncols));
}
__device__ __forceinline__ void tc_relinquish() {
    asm volatile("tcgen05.relinquish_alloc_permit.cta_group::1.sync.aligned;");
}
__device__ __forceinline__ void tc_fence_after() {
    asm volatile("tcgen05.fence::after_thread_sync;" ::: "memory");
}
__device__ __forceinline__ void tc_fence_before() {
    asm volatile("tcgen05.fence::before_thread_sync;" ::: "memory");
}
__device__ __forceinline__ void tc_wait_ld() {
    asm volatile("tcgen05.wait::ld.sync.aligned;" ::: "memory");
}
__device__ __forceinline__ void mma_f16_ss(uint32_t d_tmem, uint64_t a_desc, uint64_t b_desc,
                                           uint32_t idesc, bool accum) {
    uint32_t en = accum ? 1u : 0u;
    asm volatile(
        "{\n\t.reg .pred p;\n\t"
        "setp.ne.u32 p, %4, 0;\n\t"
        "tcgen05.mma.cta_group::1.kind::f16 [%0], %1, %2, %3, {%5, %5, %5, %5}, p;\n\t}"
        :: "r"(d_tmem), "l"(a_desc), "l"(b_desc), "r"(idesc), "r"(en), "r"(0u)
        : "memory");
}
#define TC_LD_X32(r, addr)                                                     \
    asm volatile("tcgen05.ld.sync.aligned.32x32b.x32.b32 "                     \
        "{%0,%1,%2,%3,%4,%5,%6,%7,%8,%9,%10,%11,%12,%13,%14,%15,"              \
        "%16,%17,%18,%19,%20,%21,%22,%23,%24,%25,%26,%27,%28,%29,%30,%31}, [%32];" \
        : "=r"((r)[0]),"=r"((r)[1]),"=r"((r)[2]),"=r"((r)[3]),                 \
          "=r"((r)[4]),"=r"((r)[5]),"=r"((r)[6]),"=r"((r)[7]),                 \
          "=r"((r)[8]),"=r"((r)[9]),"=r"((r)[10]),"=r"((r)[11]),               \
          "=r"((r)[12]),"=r"((r)[13]),"=r"((r)[14]),"=r"((r)[15]),             \
          "=r"((r)[16]),"=r"((r)[17]),"=r"((r)[18]),"=r"((r)[19]),             \
          "=r"((r)[20]),"=r"((r)[21]),"=r"((r)[22]),"=r"((r)[23]),             \
          "=r"((r)[24]),"=r"((r)[25]),"=r"((r)[26]),"=r"((r)[27]),             \
          "=r"((r)[28]),"=r"((r)[29]),"=r"((r)[30]),"=r"((r)[31])              \
        : "r"(addr))
static __device__ __forceinline__ uint64_t make_desc(uint32_t addr) {
    return (uint64_t(2) << 61) | (uint64_t(1) << 46) | (uint64_t(64) << 32)
         | (uint64_t(1) << 16) | ((uint64_t)(addr >> 4) & 0x3FFF);
}
// idesc: dtype F32, atype=btype=F16, N=256, M=128
#define TC_IDESC ((1u << 4) | (32u << 17) | (8u << 24))
#endif  // __CUDA_ARCH_FEAT_SM103_ALL

// ---- fused prep: routing + activation convert + weight convert --------------
struct PrepArgs {
    const float* img;  const float* txt;
    const float* Wrq;  const float* Wrk;
    const float* wsrc[5];
    __half*      wdst[5];
    int          wend[5];   // cumulative, 8-elem units
};

__global__ void prep_kernel(PrepArgs a) {
    if (blockIdx.x < ROUTE_BLOCKS) {
        // ---------------- routing + activation fp32->fp16 ------------------
        int gw   = blockIdx.x * 8 + (threadIdx.x >> 5);   // 0..16383
        int lane = threadIdx.x & 31;
        int side = gw >> 13;                               // 0: img, 1: txt
        int tok  = gw & (MROWS - 1);

        const float* x;  const float* wr;  __half* y;  int dim;
        if (side == 0) { x = a.img + (size_t)tok * IMG_DIM; wr = a.Wrq;
                         y = c_img + (size_t)tok * IMG_DIM; dim = IMG_DIM; }
        else           { x = a.txt + (size_t)tok * TXT_DIM; wr = a.Wrk;
                         y = c_txt + (size_t)tok * TXT_DIM; dim = TXT_DIM; }

        float s0 = 0.f, s1 = 0.f, s2 = 0.f;
        for (int k0 = 0; k0 < dim; k0 += 128) {
            int k = k0 + lane * 4;
            float4 xv = *reinterpret_cast<const float4*>(x + k);

            __half2 h0 = __floats2half2_rn(xv.x, xv.y);
            __half2 h1 = __floats2half2_rn(xv.z, xv.w);
            uint2 o;
            o.x = *reinterpret_cast<uint32_t*>(&h0);
            o.y = *reinterpret_cast<uint32_t*>(&h1);
            *reinterpret_cast<uint2*>(y + k) = o;

            float4 w0 = *reinterpret_cast<const float4*>(wr + k);
            float4 w1 = *reinterpret_cast<const float4*>(wr + dim + k);
            float4 w2 = *reinterpret_cast<const float4*>(wr + 2 * dim + k);
            s0 = __fmaf_rn(xv.x, w0.x, s0); s0 = __fmaf_rn(xv.y, w0.y, s0);
            s0 = __fmaf_rn(xv.z, w0.z, s0); s0 = __fmaf_rn(xv.w, w0.w, s0);
            s1 = __fmaf_rn(xv.x, w1.x, s1); s1 = __fmaf_rn(xv.y, w1.y, s1);
            s1 = __fmaf_rn(xv.z, w1.z, s1); s1 = __fmaf_rn(xv.w, w1.w, s1);
            s2 = __fmaf_rn(xv.x, w2.x, s2); s2 = __fmaf_rn(xv.y, w2.y, s2);
            s2 = __fmaf_rn(xv.z, w2.z, s2); s2 = __fmaf_rn(xv.w, w2.w, s2);
        }
        #pragma unroll
        for (int off = 16; off; off >>= 1) {
            s0 += __shfl_down_sync(0xffffffffu, s0, off);
            s1 += __shfl_down_sync(0xffffffffu, s1, off);
            s2 += __shfl_down_sync(0xffffffffu, s2, off);
        }

        double v0 = 0, v1 = 0, v2 = 0;
        int need64 = 0;
        if (lane == 0) {
            v0 = (double)s0; v1 = (double)s1; v2 = (double)s2;
            double hi = v0 > v1 ? (v0 > v2 ? v0 : v2) : (v1 > v2 ? v1 : v2);
            double mid = v0 + v1 + v2
                       - hi
                       - (v0 < v1 ? (v0 < v2 ? v0 : v2) : (v1 < v2 ? v1 : v2));
            need64 = (hi - mid) < 1e-2;
        }
        need64 = __shfl_sync(0xffffffffu, need64, 0);

        if (need64) {   // rare: exact fp64 recompute, warp-wide
            double d0 = 0, d1 = 0, d2 = 0;
            for (int k = lane; k < dim; k += 32) {
                double xv = (double)x[k];
                d0 += xv * (double)wr[k];
                d1 += xv * (double)wr[dim + k];
                d2 += xv * (double)wr[2 * dim + k];
            }
            #pragma unroll
            for (int off = 16; off; off >>= 1) {
                d0 += __shfl_down_sync(0xffffffffu, d0, off);
                d1 += __shfl_down_sync(0xffffffffu, d1, off);
                d2 += __shfl_down_sync(0xffffffffu, d2, off);
            }
            if (lane == 0) { v0 = d0; v1 = d1; v2 = d2; }
        }

        if (lane == 0) {
            int p = 0; double best = v0;
            if (v1 > best) { best = v1; p = 1; }
            if (v2 > best) { best = v2; p = 2; }
            int pos = atomicAdd(&g_cnt[side * 3 + p], 1);
            g_list[side * 3 + p][pos] = tok;
        }
    } else {
        // ---------------- weight fp32 -> fp16 -------------------------------
        const int bid = blockIdx.x - ROUTE_BLOCKS;
        const int total = a.wend[4];
        const int stride = WCONV_BLOCKS * blockDim.x;
        for (int i = bid * blockDim.x + threadIdx.x; i < total; i += stride) {
            int s = 0;
            #pragma unroll
            for (int t = 0; t < 4; t++) s += (i >= a.wend[t]);
            int j = i - (s ? a.wend[s - 1] : 0);
            const float4* p = reinterpret_cast<const float4*>(a.wsrc[s]) + 2 * (size_t)j;
            float4 x = p[0], y = p[1];
            __half2 h0 = __floats2half2_rn(x.x, x.y);
            __half2 h1 = __floats2half2_rn(x.z, x.w);
            __half2 h2 = __floats2half2_rn(y.x, y.y);
            __half2 h3 = __floats2half2_rn(y.z, y.w);
            uint4 o;
            o.x = *reinterpret_cast<uint32_t*>(&h0);
            o.y = *reinterpret_cast<uint32_t*>(&h1);
            o.z = *reinterpret_cast<uint32_t*>(&h2);
            o.w = *reinterpret_cast<uint32_t*>(&h3);
            reinterpret_cast<uint4*>(a.wdst[s])[j] = o;
        }
    }
}

// ---- fused GEMM (unchanged from round 14, proven) --------------------------
#define KC        64
#define A_HALF    (128 * 128)
#define A_BYTES   (2 * A_HALF)
#define B_BYTES   (256 * 128)
#define STG_BYTES (A_BYTES + B_BYTES)
#define STAGES    3
#define CTRL_OFF  (STAGES * STG_BYTES)    /* 192 KB */
#define SMEM_TOTAL (CTRL_OFF + 2048)
#define GRID_X    166
#define FB_STG_BYTES (A_HALF + B_BYTES)
#define FB_STAGES    3

__global__ void __launch_bounds__(256, 1)
hmma_gemm(float* __restrict__ out)
{
    extern __shared__ char smem[];
    const int bx = blockIdx.x;

    const __half* A;  const __half* W;
    long long outBase;  int K, slot, rowBase;

    if (bx < 96) {
        int g = bx >> 5, t = bx & 31;
        rowBase = t * 256;  slot = -1;
        if (g == 0)      { A = c_img; W = c_wq; outBase = 0;          K = IMG_DIM; }
        else if (g == 1) { A = c_txt; W = c_wk; outBase = TELEMS;     K = TXT_DIM; }
        else             { A = c_txt; W = c_wv; outBase = 2 * TELEMS; K = TXT_DIM; }
    } else if (bx < 131) {
        int t = bx - 96;
        int c0 = (g_cnt[0] + 255) >> 8, c1 = (g_cnt[1] + 255) >> 8,
            c2 = (g_cnt[2] + 255) >> 8;
        int p, loc;
        if (t < c0)            { p = 0; loc = t; }
        else if (t < c0 + c1)  { p = 1; loc = t - c0; }
        else if (t < c0 + c1 + c2) { p = 2; loc = t - c0 - c1; }
        else return;
        A = c_img;  W = c_wqb + (size_t)p * INNER * IMG_DIM;
        outBase = 3 * TELEMS;  K = IMG_DIM;  slot = p;  rowBase = loc * 256;
    } else {
        int t = bx - 131;
        int c0 = (g_cnt[3] + 255) >> 8, c1 = (g_cnt[4] + 255) >> 8,
            c2 = (g_cnt[5] + 255) >> 8;
        int p, loc;
        if (t < c0)            { p = 0; loc = t; }
        else if (t < c0 + c1)  { p = 1; loc = t - c0; }
        else if (t < c0 + c1 + c2) { p = 2; loc = t - c0 - c1; }
        else return;
        A = c_txt;  W = c_wkb + (size_t)p * INNER * TXT_DIM;
        outBase = 4 * TELEMS;  K = TXT_DIM;  slot = 3 + p;  rowBase = loc * 256;
    }

    const int NCHUNK = K / KC;
    const int colBase = blockIdx.y * 256;
    const int cnt = (slot >= 0) ? g_cnt[slot] : MROWS;

    const int tid  = threadIdx.x;
    const int wid  = tid >> 5;
    const int lane = tid & 31;

    const uint32_t sb = smem_u32(smem);
    int* s_rowmap = (int*)(smem + CTRL_OFF);
    if (tid < 256) {
        int gr = rowBase + tid;
        s_rowmap[tid] = (slot < 0) ? gr : ((gr < cnt) ? g_list[slot][gr] : 0);
    }

#if defined(__CUDA_ARCH_FEAT_SM103_ALL)
    // ======================= tcgen05 path: 256x256 ==========================
    auto load_stage = [&](int buf, int chunk) {
        const int kc = chunk * KC;
        const uint32_t base = sb + buf * STG_BYTES;
        #pragma unroll
        for (int j = 0; j < 8; j++) {
            int t = tid + j * 256;
            int r = t >> 3, c = t & 7;
            const __half* g = A + (size_t)s_rowmap[r] * K + kc + c * 8;
            cp16(base + (r >> 7) * A_HALF + SWZ((r & 127) * 128 + c * 16), g);
        }
        #pragma unroll
        for (int j = 0; j < 8; j++) {
            int t = tid + j * 256;
            int r = t >> 3, c = t & 7;
            const __half* g = W + (size_t)(colBase + r) * K + kc + c * 8;
            cp16(base + A_BYTES + SWZ(r * 128 + c * 16), g);
        }
    };

    const uint32_t mbar0 = sb + CTRL_OFF + 1536;
    const uint32_t tptr  = sb + CTRL_OFF + 1600;
    if (tid == 0)
        for (int s = 0; s < STAGES; s++) mbar_init(mbar0 + 8 * s, 1);
    if (wid == 0) tc_alloc(tptr, 512);
    __syncthreads();

    uint32_t tmem;
    asm volatile("ld.shared.b32 %0, [%1];" : "=r"(tmem) : "r"(tptr));

    load_stage(0, 0); cp_commit();
    load_stage(1, 1); cp_commit();

    int ph[STAGES];
    #pragma unroll
    for (int s = 0; s < STAGES; s++) ph[s] = 0;

    for (int i = 0; i < NCHUNK; i++) {
        const int buf = i % STAGES;
        cp_wait<STAGES - 2>();
        fence_gen_to_async();
        __syncthreads();

        if (tid == 0) {
            uint64_t ad0 = make_desc(sb + buf * STG_BYTES);
            uint64_t ad1 = make_desc(sb + buf * STG_BYTES + A_HALF);
            uint64_t bd  = make_desc(sb + buf * STG_BYTES + A_BYTES);
            #pragma unroll
            for (int ks = 0; ks < 4; ks++) {
                bool acc = (i > 0) || (ks > 0);
                mma_f16_ss(tmem,       ad0 + ks * 2, bd + ks * 2, TC_IDESC, acc);
                mma_f16_ss(tmem + 256, ad1 + ks * 2, bd + ks * 2, TC_IDESC, acc);
            }
            tc_commit(mbar0 + 8 * buf);
        }

        if (i + 2 < NCHUNK) {
            if (i >= 1) {
                int pb = (i - 1) % STAGES;
                mbar_wait(mbar0 + 8 * pb, ph[pb]);
                ph[pb] ^= 1;
            }
            load_stage((i + 2) % STAGES, i + 2);
        }
        cp_commit();
    }

    {
        int lb = (NCHUNK - 1) % STAGES;
        mbar_wait(mbar0 + 8 * lb, ph[lb]);
    }
    tc_fence_after();

    {
        const int sp  = wid & 3;
        const int mh  = wid >> 2;
        const int row = mh * 128 + sp * 32 + lane;
        const bool valid = (rowBase + row) < cnt;
        const int mt = s_rowmap[row];
        const int bb = mt >> 10, sq = mt & 1023;
        #pragma unroll
        for (int cc = 0; cc < 8; cc++) {
            uint32_t r[32];
            TC_LD_X32(r, tmem + mh * 256 + cc * 32);
            tc_wait_ld();
            if (valid) {
                const int n0 = colBase + cc * 32;
                const int h = n0 >> 6, d0 = n0 & 63;
                long long off = outBase + (((long long)(bb * 16 + h) * 1024 + sq) * 64) + d0;
                float4* p = reinterpret_cast<float4*>(out + off);
                #pragma unroll
                for (int q = 0; q < 8; q++)
                    p[q] = make_float4(__uint_as_float(r[4 * q + 0]),
                                       __uint_as_float(r[4 * q + 1]),
                                       __uint_as_float(r[4 * q + 2]),
                                       __uint_as_float(r[4 * q + 3]));
            }
        }
    }
    tc_fence_before();
    __syncthreads();
    if (wid == 0) {
        tc_relinquish();
        tc_dealloc(tmem, 512);
    }
#else
    // ============ HMMA fallback: two sequential M=128 passes ================
    __syncthreads();

    const int wm = (wid & 1) * 64;
    const int wn = (wid >> 1) * 64;

    for (int mh = 0; mh < 2; mh++) {
        auto load_stage_f = [&](int buf, int chunk) {
            const int kc = chunk * KC;
            const uint32_t base = sb + buf * FB_STG_BYTES;
            #pragma unroll
            for (int j = 0; j < 4; j++) {
                int t = tid + j * 256;
                int r = t >> 3, c = t & 7;
                const __half* g = A + (size_t)s_rowmap[mh * 128 + r] * K + kc + c * 8;
                cp16(base + SWZ(r * 128 + c * 16), g);
            }
            #pragma unroll
            for (int j = 0; j < 8; j++) {
                int t = tid + j * 256;
                int r = t >> 3, c = t & 7;
                const __half* g = W + (size_t)(colBase + r) * K + kc + c * 8;
                cp16(base + A_HALF + SWZ(r * 128 + c * 16), g);
            }
        };

        float acc[4][8][4];
        #pragma unroll
        for (int m = 0; m < 4; m++)
            #pragma unroll
            for (int n = 0; n < 8; n++)
                #pragma unroll
                for (int q = 0; q < 4; q++) acc[m][n][q] = 0.f;

        load_stage_f(0, 0); cp_commit();
        load_stage_f(1, 1); cp_commit();

        for (int c = 0; c < NCHUNK; c++) {
            const int buf = c % FB_STAGES;
            cp_wait<FB_STAGES - 2>();
            __syncthreads();

            if (c + 2 < NCHUNK) load_stage_f((c + 2) % FB_STAGES, c + 2);
            cp_commit();

            const uint32_t aB = sb + buf * FB_STG_BYTES;
            const uint32_t bB = aB + A_HALF;

            #pragma unroll
            for (int ks = 0; ks < 4; ks++) {
                uint32_t a[4][4];
                #pragma unroll
                for (int m = 0; m < 4; m++) {
                    int row = wm + m * 16 + (lane & 15);
                    int c16 = ks * 2 + (lane >> 4);
                    ldsm_x4(a[m][0], a[m][1], a[m][2], a[m][3],
                            aB + SWZ(row * 128 + c16 * 16));
                }
                uint32_t b[8][2];
                #pragma unroll
                for (int t = 0; t < 4; t++) {
                    int nrow = wn + t * 16 + (lane & 7) + ((lane >> 4) << 3);
                    int c16  = ks * 2 + ((lane >> 3) & 1);
                    uint32_t r0, r1, r2, r3;
                    ldsm_x4(r0, r1, r2, r3, bB + SWZ(nrow * 128 + c16 * 16));
                    b[2 * t][0] = r0;     b[2 * t][1] = r1;
                    b[2 * t + 1][0] = r2; b[2 * t + 1][1] = r3;
                }
                #pragma unroll
                for (int m = 0; m < 4; m++)
                    #pragma unroll
                    for (int n = 0; n < 8; n++)
                        mma16816(acc[m][n], a[m], b[n]);
            }
            __syncthreads();
        }

        const int head = (colBase + wn) >> 6;
        #pragma unroll
        for (int m = 0; m < 4; m++) {
            #pragma unroll
            for (int half = 0; half < 2; half++) {
                int rr = mh * 128 + wm + m * 16 + (lane >> 2) + half * 8;
                if (rowBase + rr >= cnt) continue;
                int mt = s_rowmap[rr];
                int bb = mt >> 10, sq = mt & 1023;
                long long off0 = outBase + (((long long)(bb * 16 + head) * 1024 + sq) * 64);
                #pragma unroll
                for (int n = 0; n < 8; n++) {
                    int dd = n * 8 + 2 * (lane & 3);
                    float2 v = make_float2(acc[m][n][half * 2], acc[m][n][half * 2 + 1]);
                    *reinterpret_cast<float2*>(out + off0 + dd) = v;
                }
            }
        }
        __syncthreads();
    }
#endif
}

// ---- host ------------------------------------------------------------------
extern "C" void kernel_launch(void* const* d_in, const int* in_sizes, int n_in,
                              void* d_out, int out_size) {
    (void)in_sizes; (void)n_in; (void)out_size;
    const float* img = (const float*)d_in[0];
    const float* txt = (const float*)d_in[1];
    const float* Wq  = (const float*)d_in[2];
    const float* Wk  = (const float*)d_in[3];
    const float* Wv  = (const float*)d_in[4];
    const float* Wqb = (const float*)d_in[5];
    const float* Wkb = (const float*)d_in[6];
    const float* Wrq = (const float*)d_in[7];
    const float* Wrk = (const float*)d_in[8];
    float* out = (float*)d_out;

    cudaFuncSetAttribute(hmma_gemm, cudaFuncAttributeMaxDynamicSharedMemorySize,
                         SMEM_TOTAL);

    __half *p_wq, *p_wk, *p_wv, *p_wqb, *p_wkb;
    cudaGetSymbolAddress((void**)&p_wq,  c_wq);
    cudaGetSymbolAddress((void**)&p_wk,  c_wk);
    cudaGetSymbolAddress((void**)&p_wv,  c_wv);
    cudaGetSymbolAddress((void**)&p_wqb, c_wqb);
    cudaGetSymbolAddress((void**)&p_wkb, c_wkb);

    // g_cnt = 0 as a graph-capturable memset node (must precede prep atomics).
    int* p_gcnt;
    cudaGetSymbolAddress((void**)&p_gcnt, g_cnt);
    cudaMemsetAsync(p_gcnt, 0, 6 * sizeof(int));

    PrepArgs pa;
    pa.img = img;  pa.txt = txt;  pa.Wrq = Wrq;  pa.Wrk = Wrk;
    const float* srcs[5] = { Wq, Wk, Wv, Wqb, Wkb };
    __half* dsts[5] = { p_wq, p_wk, p_wv, p_wqb, p_wkb };
    int lens[5] = { INNER * IMG_DIM / 8, INNER * TXT_DIM / 8, INNER * TXT_DIM / 8,
                    3 * INNER * IMG_DIM / 8, 3 * INNER * TXT_DIM / 8 };
    int accum = 0;
    for (int i = 0; i < 5; i++) {
        pa.wsrc[i] = srcs[i];
        pa.wdst[i] = dsts[i];
        accum += lens[i];
        pa.wend[i] = accum;
    }

    prep_kernel<<<PREP_BLOCKS, 256>>>(pa);
    hmma_gemm<<<dim3(GRID_X, 4), 256, SMEM_TOTAL>>>(out);
}